// round 2
// baseline (speedup 1.0000x reference)
#include <cuda_runtime.h>
#include <cstdint>
#include <cstddef>

#define DV 128
#define DE 64
#define MAXN 50000
typedef unsigned long long ull;

__device__ __forceinline__ void ffma2(ull &acc, ull a, ull b) {
    asm("fma.rn.f32x2 %0, %1, %2, %0;" : "+l"(acc) : "l"(a), "l"(b));
}
__device__ __forceinline__ ull pack2(float lo, float hi) {
    ull r; asm("mov.b64 %0, {%1, %2};" : "=l"(r) : "f"(lo), "f"(hi)); return r;
}
__device__ __forceinline__ float2 unpack2(ull v) {
    float lo, hi; asm("mov.b64 {%0, %1}, %2;" : "=f"(lo), "=f"(hi) : "l"(v));
    return make_float2(lo, hi);
}

// combined weights:
// g_Wnode[k][c] k<128: c [0,64)=WQ  [64,128)=WK  [128,320)=WV@Wu_a  [320,512)=WV@Wu_b
// g_Wedge[k][c] k<64 : c [0,64)=WE  [64,256)=WE@Wu_c
__device__ __align__(16) float g_Wnode[128 * 512];
__device__ __align__(16) float g_Wedge[64 * 256];
__device__ float g_bnode[512];
__device__ float g_bedge[256];
__device__ __align__(16) float g_G[(size_t)MAXN * 512];  // per node: [Q|K|P1|P2]
__device__ int g_idx64;

__global__ void zero_kernel(float4* out, int n4) {
    for (int i = blockIdx.x * blockDim.x + threadIdx.x; i < n4; i += gridDim.x * blockDim.x)
        out[i] = make_float4(0.f, 0.f, 0.f, 0.f);
}

__global__ void detect_kernel(const int* a, const int* b, int E) {
    if (threadIdx.x == 0) {
        int n = E < 64 ? E : 64, ok = 1;
        for (int i = 0; i < n; i++)
            if (a[2 * i + 1] != 0 || b[2 * i + 1] != 0) ok = 0;
        g_idx64 = ok;
    }
}

__global__ void setup_kernel(const float* __restrict__ WQ, const float* __restrict__ bQ,
                             const float* __restrict__ WK, const float* __restrict__ bK,
                             const float* __restrict__ WV, const float* __restrict__ bV,
                             const float* __restrict__ WE, const float* __restrict__ bE,
                             const float* __restrict__ Wu, const float* __restrict__ bu) {
    const int total = 65536 + 16384 + 512 + 256;
    for (int t = blockIdx.x * blockDim.x + threadIdx.x; t < total; t += gridDim.x * blockDim.x) {
        float v;
        if (t < 65536) {
            int d = t >> 9, c = t & 511;
            if (c < 64)       v = WQ[d * 64 + c];
            else if (c < 128) v = WK[d * 64 + (c - 64)];
            else {
                int j = (c < 320) ? (c - 128) : (c - 320);
                int rb = (c < 320) ? 0 : 64;
                float s = 0.f;
                #pragma unroll 8
                for (int k = 0; k < 64; k++) s += WV[d * 64 + k] * Wu[(rb + k) * 192 + j];
                v = s;
            }
            g_Wnode[t] = v;
        } else if (t < 81920) {
            int t2 = t - 65536, r = t2 >> 8, c = t2 & 255;
            if (c < 64) v = WE[r * 64 + c];
            else {
                int j = c - 64; float s = 0.f;
                #pragma unroll 8
                for (int k = 0; k < 64; k++) s += WE[r * 64 + k] * Wu[(128 + k) * 192 + j];
                v = s;
            }
            g_Wedge[t2] = v;
        } else if (t < 82432) {
            int i = t - 81920;
            if (i < 64)       v = bQ[i];
            else if (i < 128) v = bK[i - 64];
            else {
                int j = (i < 320) ? (i - 128) : (i - 320);
                int rb = (i < 320) ? 0 : 64;
                float s = 0.f;
                #pragma unroll 8
                for (int k = 0; k < 64; k++) s += bV[k] * Wu[(rb + k) * 192 + j];
                v = s;
            }
            g_bnode[i] = v;
        } else {
            int j = t - 82496;  // t-82432-64 when in EU part
            int i = t - 82432;
            if (i < 64) v = bE[i];
            else {
                float s = bu[j];
                #pragma unroll 8
                for (int k = 0; k < 64; k++) s += bE[k] * Wu[(128 + k) * 192 + j];
                v = s;
            }
            g_bedge[i] = v;
        }
    }
}

// G = node_fea @ g_Wnode + g_bnode ; tile 32 rows x 512 cols
__global__ void __launch_bounds__(256) node_kernel(const float* __restrict__ nf, int N) {
    __shared__ float sA[32 * 260];
    const int tid = threadIdx.x, tile = blockIdx.x * 32;
    #pragma unroll
    for (int i = tid; i < 32 * 32; i += 256) {
        int r = i >> 5, c4 = (i & 31) << 2, n = tile + r;
        float4 v = make_float4(0.f, 0.f, 0.f, 0.f);
        if (n < N) v = *(const float4*)(nf + (size_t)n * 128 + c4);
        float2* dst = (float2*)(sA + r * 260 + 2 * c4);
        dst[0] = make_float2(v.x, v.x); dst[1] = make_float2(v.y, v.y);
        dst[2] = make_float2(v.z, v.z); dst[3] = make_float2(v.w, v.w);
    }
    __syncthreads();
    const int cg = tid & 63, rg = tid >> 6, c0 = cg * 8, r0 = rg * 8;
    ull acc[8][4];
    #pragma unroll
    for (int p = 0; p < 4; p++) {
        ull bb = pack2(g_bnode[c0 + 2 * p], g_bnode[c0 + 2 * p + 1]);
        #pragma unroll
        for (int r = 0; r < 8; r++) acc[r][p] = bb;
    }
    #pragma unroll 4
    for (int k = 0; k < 128; k++) {
        ulonglong2 w0 = *(const ulonglong2*)(g_Wnode + k * 512 + c0);
        ulonglong2 w1 = *(const ulonglong2*)(g_Wnode + k * 512 + c0 + 4);
        #pragma unroll
        for (int r = 0; r < 8; r++) {
            ull a2 = *(const ull*)(sA + (r0 + r) * 260 + 2 * k);
            ffma2(acc[r][0], a2, w0.x); ffma2(acc[r][1], a2, w0.y);
            ffma2(acc[r][2], a2, w1.x); ffma2(acc[r][3], a2, w1.y);
        }
    }
    #pragma unroll
    for (int r = 0; r < 8; r++) {
        int n = tile + r0 + r;
        if (n < N) {
            float2 p0 = unpack2(acc[r][0]), p1 = unpack2(acc[r][1]);
            float2 p2 = unpack2(acc[r][2]), p3 = unpack2(acc[r][3]);
            float4* dst = (float4*)(g_G + (size_t)n * 512 + c0);
            dst[0] = make_float4(p0.x, p0.y, p1.x, p1.y);
            dst[1] = make_float4(p2.x, p2.y, p3.x, p3.y);
        }
    }
}

constexpr int TE = 64;
constexpr int SEPU_S = 260;   // row: [0,64)=Ep, [64,256)=EU -> mij
constexpr int SE_S   = 136;   // duplicated edge_fea tile
constexpr int SMSG_S = 132;   // msg tile (aliases sU)
constexpr int SM_FLOATS = TE * SEPU_S + TE * SE_S;
constexpr int SMEM_EDGE_BYTES = SM_FLOATS * 4 + 2 * TE * 4;

__global__ void __launch_bounds__(256, 2) edge_kernel(
    const float* __restrict__ edge_fea,
    const void* __restrict__ idx1v, const void* __restrict__ idx2v,
    const float* __restrict__ Wm, const float* __restrict__ bm,
    const float* __restrict__ g1, const float* __restrict__ b1,
    const float* __restrict__ g2, const float* __restrict__ b2,
    float* __restrict__ out, int E)
{
    extern __shared__ float sm[];
    float* sEPU = sm;
    float* sU   = sm + TE * SEPU_S;
    int* sI1 = (int*)(sm + SM_FLOATS);
    int* sI2 = sI1 + TE;
    const int tid = threadIdx.x, e0 = blockIdx.x * TE;

    if (tid < TE) {
        int e = e0 + tid, i1 = 0, i2 = 0;
        if (e < E) {
            if (g_idx64) {
                i1 = (int)((const long long*)idx1v)[e];
                i2 = (int)((const long long*)idx2v)[e];
            } else {
                i1 = ((const int*)idx1v)[e];
                i2 = ((const int*)idx2v)[e];
            }
        }
        sI1[tid] = i1; sI2[tid] = i2;
    }
    #pragma unroll
    for (int i = tid; i < TE * 16; i += 256) {
        int r = i >> 4, c4 = (i & 15) << 2, e = e0 + r;
        float4 v = make_float4(0.f, 0.f, 0.f, 0.f);
        if (e < E) v = *(const float4*)(edge_fea + (size_t)e * DE + c4);
        float2* dst = (float2*)(sU + r * SE_S + 2 * c4);
        dst[0] = make_float2(v.x, v.x); dst[1] = make_float2(v.y, v.y);
        dst[2] = make_float2(v.z, v.z); dst[3] = make_float2(v.w, v.w);
    }
    __syncthreads();

    // GEMM1: sEPU[64][256] = edge_tile @ g_Wedge + g_bedge
    {
        const int cg = tid & 31, rg = tid >> 5, c0 = cg * 8, r0 = rg * 8;
        ull acc[8][4];
        #pragma unroll
        for (int p = 0; p < 4; p++) {
            ull bb = pack2(g_bedge[c0 + 2 * p], g_bedge[c0 + 2 * p + 1]);
            #pragma unroll
            for (int r = 0; r < 8; r++) acc[r][p] = bb;
        }
        #pragma unroll 4
        for (int k = 0; k < DE; k++) {
            ulonglong2 w0 = *(const ulonglong2*)(g_Wedge + k * 256 + c0);
            ulonglong2 w1 = *(const ulonglong2*)(g_Wedge + k * 256 + c0 + 4);
            #pragma unroll
            for (int r = 0; r < 8; r++) {
                ull a2 = *(const ull*)(sU + (r0 + r) * SE_S + 2 * k);
                ffma2(acc[r][0], a2, w0.x); ffma2(acc[r][1], a2, w0.y);
                ffma2(acc[r][2], a2, w1.x); ffma2(acc[r][3], a2, w1.y);
            }
        }
        #pragma unroll
        for (int r = 0; r < 8; r++) {
            float2* dst = (float2*)(sEPU + (r0 + r) * SEPU_S + c0);
            #pragma unroll
            for (int p = 0; p < 4; p++) dst[p] = unpack2(acc[r][p]);
        }
    }
    __syncthreads();

    // attention + LN1 + sigmoid gate; mij written in place over EU
    {
        const int e = tid >> 2, ts = tid & 3, jb = ts * 48;
        const float* B1 = g_G + (size_t)sI1[e] * 512;
        const float* B2 = g_G + (size_t)sI2[e] * 512;
        const float* EP = sEPU + e * SEPU_S;
        const float INV = 0.07216878364870323f;  // 1/sqrt(192)
        float s1 = 0.f, s2 = 0.f;
        #pragma unroll
        for (int jj = 0; jj < 48; jj++) {
            int j = jb + jj;
            float qv = __ldg(B1 + (j & 63));
            float kv = (j < 64) ? __ldg(B1 + 64 + j)
                     : (j < 128) ? __ldg(B2 + j) : EP[j - 128];
            float a = qv * kv * INV;
            s1 += a; s2 += a * a;
        }
        s1 += __shfl_xor_sync(0xffffffffu, s1, 1);
        s2 += __shfl_xor_sync(0xffffffffu, s2, 1);
        s1 += __shfl_xor_sync(0xffffffffu, s1, 2);
        s2 += __shfl_xor_sync(0xffffffffu, s2, 2);
        const float mean = s1 * (1.f / 192.f);
        const float rstd = rsqrtf(s2 * (1.f / 192.f) - mean * mean + 1e-5f);
        float* MI = sEPU + e * SEPU_S + 64;
        #pragma unroll
        for (int jj = 0; jj < 48; jj++) {
            int j = jb + jj;
            float qv = __ldg(B1 + (j & 63));
            float kv = (j < 64) ? __ldg(B1 + 64 + j)
                     : (j < 128) ? __ldg(B2 + j) : EP[j - 128];
            float u = __ldg(B1 + 128 + j) + __ldg(B2 + 320 + j) + MI[j];
            float x = (qv * kv * INV - mean) * rstd * __ldg(g1 + j) + __ldg(b1 + j);
            MI[j] = u / (1.f + __expf(-x));
        }
    }
    __syncthreads();

    // GEMM2: sU[64][128] = mij @ Wm + bm
    {
        const int cg = tid & 15, rg = tid >> 4, c0 = cg * 8, r0 = rg * 4;
        ull acc[4][4];
        #pragma unroll
        for (int p = 0; p < 4; p++) {
            ull bb = pack2(__ldg(bm + c0 + 2 * p), __ldg(bm + c0 + 2 * p + 1));
            #pragma unroll
            for (int r = 0; r < 4; r++) acc[r][p] = bb;
        }
        #pragma unroll 4
        for (int k = 0; k < 192; k++) {
            ulonglong2 w0 = *(const ulonglong2*)(Wm + k * 128 + c0);
            ulonglong2 w1 = *(const ulonglong2*)(Wm + k * 128 + c0 + 4);
            #pragma unroll
            for (int r = 0; r < 4; r++) {
                float m = sEPU[(r0 + r) * SEPU_S + 64 + k];
                ull a2 = pack2(m, m);
                ffma2(acc[r][0], a2, w0.x); ffma2(acc[r][1], a2, w0.y);
                ffma2(acc[r][2], a2, w1.x); ffma2(acc[r][3], a2, w1.y);
            }
        }
        #pragma unroll
        for (int r = 0; r < 4; r++) {
            float2* dst = (float2*)(sU + (r0 + r) * SMSG_S + c0);
            #pragma unroll
            for (int p = 0; p < 4; p++) dst[p] = unpack2(acc[r][p]);
        }
    }
    __syncthreads();

    // LN2 + atomic segment-sum scatter
    {
        const int r = tid >> 2, ts = tid & 3, c0 = ts * 32;
        const float* row = sU + r * SMSG_S;
        float4 vv[8];
        float s1 = 0.f, s2 = 0.f;
        #pragma unroll
        for (int q = 0; q < 8; q++) {
            vv[q] = *(const float4*)(row + c0 + q * 4);
            s1 += vv[q].x + vv[q].y + vv[q].z + vv[q].w;
            s2 += vv[q].x * vv[q].x + vv[q].y * vv[q].y + vv[q].z * vv[q].z + vv[q].w * vv[q].w;
        }
        s1 += __shfl_xor_sync(0xffffffffu, s1, 1);
        s2 += __shfl_xor_sync(0xffffffffu, s2, 1);
        s1 += __shfl_xor_sync(0xffffffffu, s1, 2);
        s2 += __shfl_xor_sync(0xffffffffu, s2, 2);
        const float mean = s1 * (1.f / 128.f);
        const float rstd = rsqrtf(s2 * (1.f / 128.f) - mean * mean + 1e-5f);
        if (e0 + r < E) {
            float* dst = out + (size_t)sI1[r] * 128 + c0;
            #pragma unroll
            for (int q = 0; q < 8; q++) {
                const float* v = (const float*)&vv[q];
                #pragma unroll
                for (int c = 0; c < 4; c++) {
                    int j = c0 + q * 4 + c;
                    atomicAdd(dst + q * 4 + c,
                              (v[c] - mean) * rstd * __ldg(g2 + j) + __ldg(b2 + j));
                }
            }
        }
    }
}

extern "C" void kernel_launch(void* const* d_in, const int* in_sizes, int n_in,
                              void* d_out, int out_size) {
    const float* nf = (const float*)d_in[0];
    const void* i1 = d_in[1];
    const void* i2 = d_in[2];
    const float* ef = (const float*)d_in[3];
    const float *WQ = (const float*)d_in[4],  *bQ = (const float*)d_in[5];
    const float *WK = (const float*)d_in[6],  *bK = (const float*)d_in[7];
    const float *WV = (const float*)d_in[8],  *bV = (const float*)d_in[9];
    const float *WE = (const float*)d_in[10], *bE = (const float*)d_in[11];
    const float *Wu = (const float*)d_in[12], *bu = (const float*)d_in[13];
    const float *Wm = (const float*)d_in[14], *bm = (const float*)d_in[15];
    const float *g1 = (const float*)d_in[16], *b1 = (const float*)d_in[17];
    const float *g2 = (const float*)d_in[18], *b2 = (const float*)d_in[19];
    const int N = in_sizes[0] / 128;
    const int E = in_sizes[3] / 64;

    cudaFuncSetAttribute(edge_kernel, cudaFuncAttributeMaxDynamicSharedMemorySize,
                         SMEM_EDGE_BYTES);

    zero_kernel<<<1024, 256>>>((float4*)d_out, out_size / 4);
    detect_kernel<<<1, 32>>>((const int*)i1, (const int*)i2, E);
    setup_kernel<<<160, 256>>>(WQ, bQ, WK, bK, WV, bV, WE, bE, Wu, bu);
    node_kernel<<<(N + 31) / 32, 256>>>(nf, N);
    edge_kernel<<<(E + 63) / 64, 256, SMEM_EDGE_BYTES>>>(
        ef, i1, i2, Wm, bm, g1, b1, g2, b2, (float*)d_out, E);
}

// round 3
// speedup vs baseline: 2.2435x; 2.2435x over previous
#include <cuda_runtime.h>
#include <cstdint>
#include <cstddef>

#define MAXN 50000
#define MAXE 800000
typedef unsigned long long ull;

__device__ __forceinline__ void ffma2(ull &acc, ull a, ull b) {
    asm("fma.rn.f32x2 %0, %1, %2, %0;" : "+l"(acc) : "l"(a), "l"(b));
}
__device__ __forceinline__ ull pack2(float lo, float hi) {
    ull r; asm("mov.b64 %0, {%1, %2};" : "=l"(r) : "f"(lo), "f"(hi)); return r;
}
__device__ __forceinline__ float2 unpack2(ull v) {
    float lo, hi; asm("mov.b64 {%0, %1}, %2;" : "=f"(lo), "=f"(hi) : "l"(v));
    return make_float2(lo, hi);
}

// g_Wnode[k][c] k<128: c [0,64)=WQ [64,128)=WK [128,320)=WV@Wu_a [320,512)=WV@Wu_b
// g_Wedge[k][c] k<64 : c [0,64)=WE [64,256)=WE@Wu_c
__device__ __align__(16) float g_Wnode[128 * 512];
__device__ __align__(16) float g_Wedge[64 * 256];
__device__ float g_bnode[512];
__device__ float g_bedge[256];
__device__ __align__(16) float g_G[(size_t)MAXN * 512];     // [Q|K|P1|P2] per node
__device__ __align__(16) float g_Mij[(size_t)MAXE * 192];   // gated mij scratch
__device__ int g_idx64;

__global__ void zero_kernel(float4* out, int n4) {
    for (int i = blockIdx.x * blockDim.x + threadIdx.x; i < n4; i += gridDim.x * blockDim.x)
        out[i] = make_float4(0.f, 0.f, 0.f, 0.f);
}

__global__ void detect_kernel(const int* a, const int* b, int E) {
    if (threadIdx.x == 0) {
        int n = E < 64 ? E : 64, ok = 1;
        for (int i = 0; i < n; i++)
            if (a[2 * i + 1] != 0 || b[2 * i + 1] != 0) ok = 0;
        g_idx64 = ok;
    }
}

__global__ void setup_kernel(const float* __restrict__ WQ, const float* __restrict__ bQ,
                             const float* __restrict__ WK, const float* __restrict__ bK,
                             const float* __restrict__ WV, const float* __restrict__ bV,
                             const float* __restrict__ WE, const float* __restrict__ bE,
                             const float* __restrict__ Wu, const float* __restrict__ bu) {
    const int total = 65536 + 16384 + 512 + 256;
    for (int t = blockIdx.x * blockDim.x + threadIdx.x; t < total; t += gridDim.x * blockDim.x) {
        float v;
        if (t < 65536) {
            int d = t >> 9, c = t & 511;
            if (c < 64)       v = WQ[d * 64 + c];
            else if (c < 128) v = WK[d * 64 + (c - 64)];
            else {
                int j = (c < 320) ? (c - 128) : (c - 320);
                int rb = (c < 320) ? 0 : 64;
                float s = 0.f;
                #pragma unroll 8
                for (int k = 0; k < 64; k++) s += WV[d * 64 + k] * Wu[(rb + k) * 192 + j];
                v = s;
            }
            g_Wnode[t] = v;
        } else if (t < 81920) {
            int t2 = t - 65536, r = t2 >> 8, c = t2 & 255;
            if (c < 64) v = WE[r * 64 + c];
            else {
                int j = c - 64; float s = 0.f;
                #pragma unroll 8
                for (int k = 0; k < 64; k++) s += WE[r * 64 + k] * Wu[(128 + k) * 192 + j];
                v = s;
            }
            g_Wedge[t2] = v;
        } else if (t < 82432) {
            int i = t - 81920;
            if (i < 64)       v = bQ[i];
            else if (i < 128) v = bK[i - 64];
            else {
                int j = (i < 320) ? (i - 128) : (i - 320);
                int rb = (i < 320) ? 0 : 64;
                float s = 0.f;
                #pragma unroll 8
                for (int k = 0; k < 64; k++) s += bV[k] * Wu[(rb + k) * 192 + j];
                v = s;
            }
            g_bnode[i] = v;
        } else {
            int i = t - 82432;
            if (i < 64) v = bE[i];
            else {
                int j = i - 64;
                float s = bu[j];
                #pragma unroll 8
                for (int k = 0; k < 64; k++) s += bE[k] * Wu[(128 + k) * 192 + j];
                v = s;
            }
            g_bedge[i] = v;
        }
    }
}

// G = node_fea @ g_Wnode + g_bnode (known-good from R2)
__global__ void __launch_bounds__(256) node_kernel(const float* __restrict__ nf, int N) {
    __shared__ float sA[32 * 260];
    const int tid = threadIdx.x, tile = blockIdx.x * 32;
    #pragma unroll
    for (int i = tid; i < 32 * 32; i += 256) {
        int r = i >> 5, c4 = (i & 31) << 2, n = tile + r;
        float4 v = make_float4(0.f, 0.f, 0.f, 0.f);
        if (n < N) v = *(const float4*)(nf + (size_t)n * 128 + c4);
        float2* dst = (float2*)(sA + r * 260 + 2 * c4);
        dst[0] = make_float2(v.x, v.x); dst[1] = make_float2(v.y, v.y);
        dst[2] = make_float2(v.z, v.z); dst[3] = make_float2(v.w, v.w);
    }
    __syncthreads();
    const int cg = tid & 63, rg = tid >> 6, c0 = cg * 8, r0 = rg * 8;
    ull acc[8][4];
    #pragma unroll
    for (int p = 0; p < 4; p++) {
        ull bb = pack2(g_bnode[c0 + 2 * p], g_bnode[c0 + 2 * p + 1]);
        #pragma unroll
        for (int r = 0; r < 8; r++) acc[r][p] = bb;
    }
    #pragma unroll 4
    for (int k = 0; k < 128; k++) {
        ulonglong2 w0 = *(const ulonglong2*)(g_Wnode + k * 512 + c0);
        ulonglong2 w1 = *(const ulonglong2*)(g_Wnode + k * 512 + c0 + 4);
        #pragma unroll
        for (int r = 0; r < 8; r++) {
            ull a2 = *(const ull*)(sA + (r0 + r) * 260 + 2 * k);
            ffma2(acc[r][0], a2, w0.x); ffma2(acc[r][1], a2, w0.y);
            ffma2(acc[r][2], a2, w1.x); ffma2(acc[r][3], a2, w1.y);
        }
    }
    #pragma unroll
    for (int r = 0; r < 8; r++) {
        int n = tile + r0 + r;
        if (n < N) {
            float2 p0 = unpack2(acc[r][0]), p1 = unpack2(acc[r][1]);
            float2 p2 = unpack2(acc[r][2]), p3 = unpack2(acc[r][3]);
            float4* dst = (float4*)(g_G + (size_t)n * 512 + c0);
            dst[0] = make_float4(p0.x, p0.y, p1.x, p1.y);
            dst[1] = make_float4(p2.x, p2.y, p3.x, p3.y);
        }
    }
}

// ================= E1: GEMM1 + attention + gate -> g_Mij =================
constexpr int SEPU_S = 260;                       // row: [0,64)=Ep [64,256)=EU
constexpr int E1_SMEM = 64 * SEPU_S * 4 + 2 * 64 * 4;

__global__ void __launch_bounds__(256, 2) e1_kernel(
    const float* __restrict__ edge_fea,
    const void* __restrict__ idx1v, const void* __restrict__ idx2v,
    const float* __restrict__ g1, const float* __restrict__ b1, int E)
{
    extern __shared__ float sm[];
    float* sEPU = sm;
    int* sI1 = (int*)(sm + 64 * SEPU_S);
    int* sI2 = sI1 + 64;
    const int tid = threadIdx.x, e0 = blockIdx.x * 64;

    if (tid < 64) {
        int e = e0 + tid, i1 = 0, i2 = 0;
        if (e < E) {
            if (g_idx64) {
                i1 = (int)((const long long*)idx1v)[e];
                i2 = (int)((const long long*)idx2v)[e];
            } else {
                i1 = ((const int*)idx1v)[e];
                i2 = ((const int*)idx2v)[e];
            }
        }
        sI1[tid] = i1; sI2[tid] = i2;
    }

    // ---- GEMM1: [64 edges] x [64 k] x [256 cols], A broadcast from global ----
    {
        const int cg = tid & 31, rg = tid >> 5;     // warp == one rg (8 rows)
        const int c0 = cg * 8, row0 = rg * 8;
        ull acc[8][4];
        #pragma unroll
        for (int p = 0; p < 4; p++) {
            ull bb = pack2(g_bedge[c0 + 2 * p], g_bedge[c0 + 2 * p + 1]);
            #pragma unroll
            for (int r = 0; r < 8; r++) acc[r][p] = bb;
        }
        #pragma unroll 2
        for (int k4 = 0; k4 < 16; k4++) {
            float4 a4[8];
            #pragma unroll
            for (int r = 0; r < 8; r++)
                a4[r] = __ldg((const float4*)(edge_fea + (size_t)(e0 + row0 + r) * 64 + k4 * 4));
            #pragma unroll
            for (int kk = 0; kk < 4; kk++) {
                int k = k4 * 4 + kk;
                ulonglong2 w0 = *(const ulonglong2*)(g_Wedge + k * 256 + c0);
                ulonglong2 w1 = *(const ulonglong2*)(g_Wedge + k * 256 + c0 + 4);
                #pragma unroll
                for (int r = 0; r < 8; r++) {
                    const float* af = (const float*)&a4[r];
                    ull a2 = pack2(af[kk], af[kk]);
                    ffma2(acc[r][0], a2, w0.x); ffma2(acc[r][1], a2, w0.y);
                    ffma2(acc[r][2], a2, w1.x); ffma2(acc[r][3], a2, w1.y);
                }
            }
        }
        #pragma unroll
        for (int r = 0; r < 8; r++) {
            float2* dst = (float2*)(sEPU + (row0 + r) * SEPU_S + c0);
            #pragma unroll
            for (int p = 0; p < 4; p++) dst[p] = unpack2(acc[r][p]);
        }
    }
    __syncthreads();

    // ---- attention + LN1 + sigmoid gate -> mij to global ----
    {
        const int e = tid >> 2, ts = tid & 3;
        const float* B1 = g_G + (size_t)sI1[e] * 512;
        const float* B2 = g_G + (size_t)sI2[e] * 512;
        const float* EProw = sEPU + e * SEPU_S;
        const float INV = 0.07216878364870323f;   // 1/sqrt(192)
        float s1 = 0.f, s2 = 0.f;
        #pragma unroll
        for (int g = 0; g < 12; g++) {
            int j0 = g * 16 + ts * 4;             // all 4 lanes same region per g
            float4 q = *(const float4*)(B1 + (j0 & 63));
            float4 kv;
            if (g < 4)      kv = *(const float4*)(B1 + 64 + j0);
            else if (g < 8) kv = *(const float4*)(B2 + j0);
            else            kv = *(const float4*)(EProw + (j0 - 128));
            float ax = q.x * kv.x * INV, ay = q.y * kv.y * INV;
            float az = q.z * kv.z * INV, aw = q.w * kv.w * INV;
            s1 += ax + ay + az + aw;
            s2 += ax * ax + ay * ay + az * az + aw * aw;
        }
        s1 += __shfl_xor_sync(0xffffffffu, s1, 1);
        s2 += __shfl_xor_sync(0xffffffffu, s2, 1);
        s1 += __shfl_xor_sync(0xffffffffu, s1, 2);
        s2 += __shfl_xor_sync(0xffffffffu, s2, 2);
        const float mean = s1 * (1.f / 192.f);
        const float rstd = rsqrtf(s2 * (1.f / 192.f) - mean * mean + 1e-5f);
        const bool wr = (e0 + e < E);
        #pragma unroll
        for (int g = 0; g < 12; g++) {
            int j0 = g * 16 + ts * 4;
            float4 q = *(const float4*)(B1 + (j0 & 63));
            float4 kv;
            if (g < 4)      kv = *(const float4*)(B1 + 64 + j0);
            else if (g < 8) kv = *(const float4*)(B2 + j0);
            else            kv = *(const float4*)(EProw + (j0 - 128));
            float4 p1 = *(const float4*)(B1 + 128 + j0);
            float4 p2 = *(const float4*)(B2 + 320 + j0);
            float4 eu = *(const float4*)(EProw + 64 + j0);
            float4 gv = __ldg((const float4*)(g1 + j0));
            float4 bv = __ldg((const float4*)(b1 + j0));
            float4 m;
            {
                float x = (q.x * kv.x * INV - mean) * rstd * gv.x + bv.x;
                m.x = (p1.x + p2.x + eu.x) / (1.f + __expf(-x));
                x = (q.y * kv.y * INV - mean) * rstd * gv.y + bv.y;
                m.y = (p1.y + p2.y + eu.y) / (1.f + __expf(-x));
                x = (q.z * kv.z * INV - mean) * rstd * gv.z + bv.z;
                m.z = (p1.z + p2.z + eu.z) / (1.f + __expf(-x));
                x = (q.w * kv.w * INV - mean) * rstd * gv.w + bv.w;
                m.w = (p1.w + p2.w + eu.w) / (1.f + __expf(-x));
            }
            if (wr) *(float4*)(g_Mij + (size_t)(e0 + e) * 192 + j0) = m;
        }
    }
}

// ================= E2: msg = mij @ Wm + bm ; LN2 ; atomic scatter =================
constexpr int SMSG_S = 132;
constexpr int E2_SMEM = 128 * SMSG_S * 4 + 128 * 4;

__global__ void __launch_bounds__(256, 2) e2_kernel(
    const void* __restrict__ idx1v,
    const float* __restrict__ Wm, const float* __restrict__ bm,
    const float* __restrict__ g2, const float* __restrict__ b2,
    float* __restrict__ out, int E)
{
    extern __shared__ float sm[];
    float* sMsg = sm;
    int* sI1 = (int*)(sm + 128 * SMSG_S);
    const int tid = threadIdx.x, e0 = blockIdx.x * 128;

    if (tid < 128) {
        int e = e0 + tid, i1 = 0;
        if (e < E) i1 = g_idx64 ? (int)((const long long*)idx1v)[e] : ((const int*)idx1v)[e];
        sI1[tid] = i1;
    }

    // GEMM2: [128 rows] x [192 k] x [128 cols]; warp = 2 rgs x 16 cgs (W dedup)
    {
        const int cg = tid & 15, rg = tid >> 4;
        const int c0 = cg * 8, row0 = rg * 8;
        ull acc[8][4];
        #pragma unroll
        for (int p = 0; p < 4; p++) {
            ull bb = pack2(__ldg(bm + c0 + 2 * p), __ldg(bm + c0 + 2 * p + 1));
            #pragma unroll
            for (int r = 0; r < 8; r++) acc[r][p] = bb;
        }
        #pragma unroll 2
        for (int k4 = 0; k4 < 48; k4++) {
            float4 a4[8];
            #pragma unroll
            for (int r = 0; r < 8; r++)
                a4[r] = *(const float4*)(g_Mij + (size_t)(e0 + row0 + r) * 192 + k4 * 4);
            #pragma unroll
            for (int kk = 0; kk < 4; kk++) {
                int k = k4 * 4 + kk;
                ulonglong2 w0 = *(const ulonglong2*)(Wm + k * 128 + c0);
                ulonglong2 w1 = *(const ulonglong2*)(Wm + k * 128 + c0 + 4);
                #pragma unroll
                for (int r = 0; r < 8; r++) {
                    const float* af = (const float*)&a4[r];
                    ull a2 = pack2(af[kk], af[kk]);
                    ffma2(acc[r][0], a2, w0.x); ffma2(acc[r][1], a2, w0.y);
                    ffma2(acc[r][2], a2, w1.x); ffma2(acc[r][3], a2, w1.y);
                }
            }
        }
        #pragma unroll
        for (int r = 0; r < 8; r++) {
            float2* dst = (float2*)(sMsg + (row0 + r) * SMSG_S + c0);
            #pragma unroll
            for (int p = 0; p < 4; p++) dst[p] = unpack2(acc[r][p]);
        }
    }
    __syncthreads();

    // LN2 + atomic segment-sum; 2 threads per row
    {
        const int r = tid >> 1, h = tid & 1, cb = h * 64;
        const float* row = sMsg + r * SMSG_S;
        float4 vv[16];
        float s1 = 0.f, s2 = 0.f;
        #pragma unroll
        for (int q = 0; q < 16; q++) {
            vv[q] = *(const float4*)(row + cb + q * 4);
            s1 += vv[q].x + vv[q].y + vv[q].z + vv[q].w;
            s2 += vv[q].x * vv[q].x + vv[q].y * vv[q].y + vv[q].z * vv[q].z + vv[q].w * vv[q].w;
        }
        s1 += __shfl_xor_sync(0xffffffffu, s1, 1);
        s2 += __shfl_xor_sync(0xffffffffu, s2, 1);
        const float mean = s1 * (1.f / 128.f);
        const float rstd = rsqrtf(s2 * (1.f / 128.f) - mean * mean + 1e-5f);
        if (e0 + r < E) {
            float* dst = out + (size_t)sI1[r] * 128 + cb;
            #pragma unroll
            for (int q = 0; q < 16; q++) {
                const float* v = (const float*)&vv[q];
                #pragma unroll
                for (int c = 0; c < 4; c++) {
                    int j = cb + q * 4 + c;
                    atomicAdd(dst + q * 4 + c,
                              (v[c] - mean) * rstd * __ldg(g2 + j) + __ldg(b2 + j));
                }
            }
        }
    }
}

extern "C" void kernel_launch(void* const* d_in, const int* in_sizes, int n_in,
                              void* d_out, int out_size) {
    const float* nf = (const float*)d_in[0];
    const void* i1 = d_in[1];
    const void* i2 = d_in[2];
    const float* ef = (const float*)d_in[3];
    const float *WQ = (const float*)d_in[4],  *bQ = (const float*)d_in[5];
    const float *WK = (const float*)d_in[6],  *bK = (const float*)d_in[7];
    const float *WV = (const float*)d_in[8],  *bV = (const float*)d_in[9];
    const float *WE = (const float*)d_in[10], *bE = (const float*)d_in[11];
    const float *Wu = (const float*)d_in[12], *bu = (const float*)d_in[13];
    const float *Wm = (const float*)d_in[14], *bm = (const float*)d_in[15];
    const float *g1 = (const float*)d_in[16], *b1 = (const float*)d_in[17];
    const float *g2 = (const float*)d_in[18], *b2 = (const float*)d_in[19];
    const int N = in_sizes[0] / 128;
    const int E = in_sizes[3] / 64;

    cudaFuncSetAttribute(e1_kernel, cudaFuncAttributeMaxDynamicSharedMemorySize, E1_SMEM);
    cudaFuncSetAttribute(e2_kernel, cudaFuncAttributeMaxDynamicSharedMemorySize, E2_SMEM);

    zero_kernel<<<1024, 256>>>((float4*)d_out, out_size / 4);
    detect_kernel<<<1, 32>>>((const int*)i1, (const int*)i2, E);
    setup_kernel<<<160, 256>>>(WQ, bQ, WK, bK, WV, bV, WE, bE, Wu, bu);
    node_kernel<<<(N + 31) / 32, 256>>>(nf, N);
    e1_kernel<<<(E + 63) / 64, 256, E1_SMEM>>>(ef, i1, i2, g1, b1, E);
    e2_kernel<<<(E + 127) / 128, 256, E2_SMEM>>>(i1, Wm, bm, g2, b2, (float*)d_out, E);
}

// round 6
// speedup vs baseline: 3.3608x; 1.4980x over previous
#include <cuda_runtime.h>
#include <cuda_bf16.h>
#include <cstdint>
#include <cstddef>

#define MAXN 50000
#define MAXE 800000
typedef unsigned long long ull;

// ---------------- scalar f32x2 helpers (node kernel) ----------------
__device__ __forceinline__ void ffma2(ull &acc, ull a, ull b) {
    asm("fma.rn.f32x2 %0, %1, %2, %0;" : "+l"(acc) : "l"(a), "l"(b));
}
__device__ __forceinline__ ull pack2(float lo, float hi) {
    ull r; asm("mov.b64 %0, {%1, %2};" : "=l"(r) : "f"(lo), "f"(hi)); return r;
}
__device__ __forceinline__ float2 unpack2(ull v) {
    float lo, hi; asm("mov.b64 {%0, %1}, %2;" : "=f"(lo), "=f"(hi) : "l"(v));
    return make_float2(lo, hi);
}

// ---------------- HMMA helpers ----------------
__device__ __forceinline__ uint32_t smem_u32(const void* p) {
    uint32_t a; asm("{ .reg .u64 t; cvta.to.shared.u64 t, %1; cvt.u32.u64 %0, t; }"
                    : "=r"(a) : "l"(p));
    return a;
}
__device__ __forceinline__ void ldsm_x4(uint32_t* a, uint32_t addr) {
    asm volatile("ldmatrix.sync.aligned.m8n8.x4.shared.b16 {%0,%1,%2,%3}, [%4];"
                 : "=r"(a[0]), "=r"(a[1]), "=r"(a[2]), "=r"(a[3]) : "r"(addr));
}
__device__ __forceinline__ void ldsm_x2(uint32_t* b, uint32_t addr) {
    asm volatile("ldmatrix.sync.aligned.m8n8.x2.shared.b16 {%0,%1}, [%2];"
                 : "=r"(b[0]), "=r"(b[1]) : "r"(addr));
}
__device__ __forceinline__ void mma_bf16(float* d, const uint32_t* a, const uint32_t* b) {
    asm volatile("mma.sync.aligned.m16n8k16.row.col.f32.bf16.bf16.f32 "
                 "{%0,%1,%2,%3},{%4,%5,%6,%7},{%8,%9},{%0,%1,%2,%3};"
                 : "+f"(d[0]), "+f"(d[1]), "+f"(d[2]), "+f"(d[3])
                 : "r"(a[0]), "r"(a[1]), "r"(a[2]), "r"(a[3]), "r"(b[0]), "r"(b[1]));
}
__device__ __forceinline__ uint32_t bf2(float a, float b) {
    __nv_bfloat162 h = __floats2bfloat162_rn(a, b);
    return *(uint32_t*)&h;
}
__device__ __forceinline__ void split2(float v, float& hi, float& lo) {
    __nv_bfloat16 h = __float2bfloat16_rn(v);
    hi = __bfloat162float(h);
    lo = v - hi;
}

// ---------------- device globals ----------------
__device__ __align__(16) float g_Wnode[128 * 512];
__device__ __align__(16) float g_Wedge[64 * 256];
__device__ float g_bnode[512];
__device__ float g_bedge[256];
__device__ __align__(16) float g_G[(size_t)MAXN * 512];
__device__ __align__(8) __nv_bfloat16 g_WeHiT[256 * 64];
__device__ __align__(8) __nv_bfloat16 g_WeLoT[256 * 64];
__device__ __align__(8) __nv_bfloat16 g_WmHiT[128 * 192];
__device__ __align__(8) __nv_bfloat16 g_WmLoT[128 * 192];
__device__ __align__(8) __nv_bfloat16 g_MijHi[(size_t)MAXE * 192];
__device__ __align__(8) __nv_bfloat16 g_MijLo[(size_t)MAXE * 192];
__device__ int g_idx64;

__global__ void zero_kernel(float4* out, int n4) {
    for (int i = blockIdx.x * blockDim.x + threadIdx.x; i < n4; i += gridDim.x * blockDim.x)
        out[i] = make_float4(0.f, 0.f, 0.f, 0.f);
}
__global__ void detect_kernel(const int* a, const int* b, int E) {
    if (threadIdx.x == 0) {
        int n = E < 64 ? E : 64, ok = 1;
        for (int i = 0; i < n; i++)
            if (a[2 * i + 1] != 0 || b[2 * i + 1] != 0) ok = 0;
        g_idx64 = ok;
    }
}

__global__ void setup_kernel(const float* __restrict__ WQ, const float* __restrict__ bQ,
                             const float* __restrict__ WK, const float* __restrict__ bK,
                             const float* __restrict__ WV, const float* __restrict__ bV,
                             const float* __restrict__ WE, const float* __restrict__ bE,
                             const float* __restrict__ Wu, const float* __restrict__ bu) {
    const int total = 65536 + 16384 + 512 + 256;
    for (int t = blockIdx.x * blockDim.x + threadIdx.x; t < total; t += gridDim.x * blockDim.x) {
        float v;
        if (t < 65536) {
            int d = t >> 9, c = t & 511;
            if (c < 64)       v = WQ[d * 64 + c];
            else if (c < 128) v = WK[d * 64 + (c - 64)];
            else {
                int j = (c < 320) ? (c - 128) : (c - 320);
                int rb = (c < 320) ? 0 : 64;
                float s = 0.f;
                #pragma unroll 8
                for (int k = 0; k < 64; k++) s += WV[d * 64 + k] * Wu[(rb + k) * 192 + j];
                v = s;
            }
            g_Wnode[t] = v;
        } else if (t < 81920) {
            int t2 = t - 65536, r = t2 >> 8, c = t2 & 255;
            if (c < 64) v = WE[r * 64 + c];
            else {
                int j = c - 64; float s = 0.f;
                #pragma unroll 8
                for (int k = 0; k < 64; k++) s += WE[r * 64 + k] * Wu[(128 + k) * 192 + j];
                v = s;
            }
            g_Wedge[t2] = v;
        } else if (t < 82432) {
            int i = t - 81920;
            if (i < 64)       v = bQ[i];
            else if (i < 128) v = bK[i - 64];
            else {
                int j = (i < 320) ? (i - 128) : (i - 320);
                int rb = (i < 320) ? 0 : 64;
                float s = 0.f;
                #pragma unroll 8
                for (int k = 0; k < 64; k++) s += bV[k] * Wu[(rb + k) * 192 + j];
                v = s;
            }
            g_bnode[i] = v;
        } else {
            int i = t - 82432;
            if (i < 64) v = bE[i];
            else {
                int j = i - 64;
                float s = bu[j];
                #pragma unroll 8
                for (int k = 0; k < 64; k++) s += bE[k] * Wu[(128 + k) * 192 + j];
                v = s;
            }
            g_bedge[i] = v;
        }
    }
}

__global__ void setup2_kernel(const float* __restrict__ Wm) {
    const int total = 16384 + 24576;
    for (int t = blockIdx.x * blockDim.x + threadIdx.x; t < total; t += gridDim.x * blockDim.x) {
        if (t < 16384) {
            int n = t >> 6, k = t & 63;
            float v = g_Wedge[k * 256 + n], hi, lo;
            split2(v, hi, lo);
            g_WeHiT[t] = __float2bfloat16_rn(hi);
            g_WeLoT[t] = __float2bfloat16_rn(lo);
        } else {
            int t2 = t - 16384, n = t2 / 192, k = t2 % 192;
            float v = Wm[k * 128 + n], hi, lo;
            split2(v, hi, lo);
            g_WmHiT[t2] = __float2bfloat16_rn(hi);
            g_WmLoT[t2] = __float2bfloat16_rn(lo);
        }
    }
}

// node kernel (unchanged, known-good)
__global__ void __launch_bounds__(256) node_kernel(const float* __restrict__ nf, int N) {
    __shared__ float sA[32 * 260];
    const int tid = threadIdx.x, tile = blockIdx.x * 32;
    #pragma unroll
    for (int i = tid; i < 32 * 32; i += 256) {
        int r = i >> 5, c4 = (i & 31) << 2, n = tile + r;
        float4 v = make_float4(0.f, 0.f, 0.f, 0.f);
        if (n < N) v = *(const float4*)(nf + (size_t)n * 128 + c4);
        float2* dst = (float2*)(sA + r * 260 + 2 * c4);
        dst[0] = make_float2(v.x, v.x); dst[1] = make_float2(v.y, v.y);
        dst[2] = make_float2(v.z, v.z); dst[3] = make_float2(v.w, v.w);
    }
    __syncthreads();
    const int cg = tid & 63, rg = tid >> 6, c0 = cg * 8, r0 = rg * 8;
    ull acc[8][4];
    #pragma unroll
    for (int p = 0; p < 4; p++) {
        ull bb = pack2(g_bnode[c0 + 2 * p], g_bnode[c0 + 2 * p + 1]);
        #pragma unroll
        for (int r = 0; r < 8; r++) acc[r][p] = bb;
    }
    #pragma unroll 4
    for (int k = 0; k < 128; k++) {
        ulonglong2 w0 = *(const ulonglong2*)(g_Wnode + k * 512 + c0);
        ulonglong2 w1 = *(const ulonglong2*)(g_Wnode + k * 512 + c0 + 4);
        #pragma unroll
        for (int r = 0; r < 8; r++) {
            ull a2 = *(const ull*)(sA + (r0 + r) * 260 + 2 * k);
            ffma2(acc[r][0], a2, w0.x); ffma2(acc[r][1], a2, w0.y);
            ffma2(acc[r][2], a2, w1.x); ffma2(acc[r][3], a2, w1.y);
        }
    }
    #pragma unroll
    for (int r = 0; r < 8; r++) {
        int n = tile + r0 + r;
        if (n < N) {
            float2 p0 = unpack2(acc[r][0]), p1 = unpack2(acc[r][1]);
            float2 p2 = unpack2(acc[r][2]), p3 = unpack2(acc[r][3]);
            float4* dst = (float4*)(g_G + (size_t)n * 512 + c0);
            dst[0] = make_float4(p0.x, p0.y, p1.x, p1.y);
            dst[1] = make_float4(p2.x, p2.y, p3.x, p3.y);
        }
    }
}

// ================= E1: HMMA GEMM1 + attention + gate -> mij (bf16 hi/lo) =================
// smem: sI1@0 sI2@512 | A_HI@2048(128x72) A_LO@20480 B_HI@38912(256x72) B_LO@75776
// sEPU (f32 [128][260]) aliases @2048 after mma.
constexpr int E1_AHI = 2048, E1_ALO = 20480, E1_BHI = 38912, E1_BLO = 75776;
constexpr int E1_SMEM = 2048 + 128 * 260 * 4;   // 135168

__global__ void __launch_bounds__(512, 1) e1_kernel(
    const float* __restrict__ edge_fea,
    const void* __restrict__ idx1v, const void* __restrict__ idx2v,
    const float* __restrict__ g1, const float* __restrict__ b1, int E)
{
    extern __shared__ char smc[];
    const uint32_t smb = smem_u32(smc);
    float* sEPU = (float*)(smc + 2048);
    int* sI1 = (int*)(smc);
    int* sI2 = (int*)(smc + 512);
    const int tid = threadIdx.x, w = tid >> 5, l = tid & 31;
    const int e0 = blockIdx.x * 128;

    if (tid < 128) {
        int e = e0 + tid, i1 = 0, i2 = 0;
        if (e < E) {
            if (g_idx64) {
                i1 = (int)((const long long*)idx1v)[e];
                i2 = (int)((const long long*)idx2v)[e];
            } else {
                i1 = ((const int*)idx1v)[e];
                i2 = ((const int*)idx2v)[e];
            }
        }
        sI1[tid] = i1; sI2[tid] = i2;
    }
    // A: edge_fea 128x64 f32 -> bf16 hi/lo, padded stride 72
    #pragma unroll
    for (int i = tid; i < 128 * 16; i += 512) {
        int r = i >> 4, c4 = (i & 15) << 2, e = e0 + r;
        float4 v = make_float4(0.f, 0.f, 0.f, 0.f);
        if (e < E) v = *(const float4*)(edge_fea + (size_t)e * 64 + c4);
        float h0, l0, h1, l1, h2, l2, h3, l3;
        split2(v.x, h0, l0); split2(v.y, h1, l1); split2(v.z, h2, l2); split2(v.w, h3, l3);
        uint32_t off = (uint32_t)(r * 72 + c4) * 2;
        *(uint32_t*)(smc + E1_AHI + off) = bf2(h0, h1);
        *(uint32_t*)(smc + E1_AHI + off + 4) = bf2(h2, h3);
        *(uint32_t*)(smc + E1_ALO + off) = bf2(l0, l1);
        *(uint32_t*)(smc + E1_ALO + off + 4) = bf2(l2, l3);
    }
    // B: WedgeT 256x64 bf16 (pre-split), stride 72
    #pragma unroll
    for (int i = tid; i < 256 * 32; i += 512) {
        int n = i >> 5, kk = (i & 31) * 2;
        uint32_t off = (uint32_t)(n * 72 + kk) * 2;
        *(uint32_t*)(smc + E1_BHI + off) = *(const uint32_t*)(g_WeHiT + n * 64 + kk);
        *(uint32_t*)(smc + E1_BLO + off) = *(const uint32_t*)(g_WeLoT + n * 64 + kk);
    }
    __syncthreads();

    // GEMM: warp w -> rows (w&7)*16, cols (w>>3)*128
    {
        const int r0 = (w & 7) * 16, cb = (w >> 3) * 128;
        float d[16][4];
        #pragma unroll
        for (int nt = 0; nt < 16; nt++)
            d[nt][0] = d[nt][1] = d[nt][2] = d[nt][3] = 0.f;
        const uint32_t aoffb = (uint32_t)((r0 + (l & 15)) * 72 + (l >> 4) * 8) * 2;
        const uint32_t boffb = (uint32_t)((cb + (l & 7)) * 72 + ((l >> 3) & 1) * 8) * 2;
        #pragma unroll
        for (int kt = 0; kt < 4; kt++) {
            uint32_t aH[4], aL[4];
            ldsm_x4(aH, smb + E1_AHI + aoffb + kt * 32);
            ldsm_x4(aL, smb + E1_ALO + aoffb + kt * 32);
            #pragma unroll
            for (int nt = 0; nt < 16; nt++) {
                uint32_t bH[2], bL[2];
                uint32_t bo = boffb + (uint32_t)(nt * 8 * 72) * 2 + kt * 32;
                ldsm_x2(bH, smb + E1_BHI + bo);
                ldsm_x2(bL, smb + E1_BLO + bo);
                mma_bf16(d[nt], aH, bH);
                mma_bf16(d[nt], aH, bL);
                mma_bf16(d[nt], aL, bH);
            }
        }
        __syncthreads();   // all tile reads done; safe to alias sEPU
        const int row = r0 + (l >> 2);
        #pragma unroll
        for (int nt = 0; nt < 16; nt++) {
            int col = cb + nt * 8 + 2 * (l & 3);
            sEPU[row * 260 + col]           = d[nt][0] + g_bedge[col];
            sEPU[row * 260 + col + 1]       = d[nt][1] + g_bedge[col + 1];
            sEPU[(row + 8) * 260 + col]     = d[nt][2] + g_bedge[col];
            sEPU[(row + 8) * 260 + col + 1] = d[nt][3] + g_bedge[col + 1];
        }
    }
    __syncthreads();

    // attention + LN1 + gate -> mij hi/lo (validated phase; 4 threads/edge)
    {
        const int e = tid >> 2, ts = tid & 3;
        const float* B1 = g_G + (size_t)sI1[e] * 512;
        const float* B2 = g_G + (size_t)sI2[e] * 512;
        const float* EProw = sEPU + e * 260;
        const float INV = 0.07216878364870323f;  // 1/sqrt(192)
        float s1 = 0.f, s2 = 0.f;
        #pragma unroll
        for (int g = 0; g < 12; g++) {
            int j0 = g * 16 + ts * 4;
            float4 q = *(const float4*)(B1 + (j0 & 63));
            float4 kv;
            if (j0 < 64)       kv = *(const float4*)(B1 + 64 + j0);
            else if (j0 < 128) kv = *(const float4*)(B2 + j0);
            else               kv = *(const float4*)(EProw + (j0 - 128));
            float ax = q.x * kv.x * INV, ay = q.y * kv.y * INV;
            float az = q.z * kv.z * INV, aw = q.w * kv.w * INV;
            s1 += ax + ay + az + aw;
            s2 += ax * ax + ay * ay + az * az + aw * aw;
        }
        s1 += __shfl_xor_sync(0xffffffffu, s1, 1);
        s2 += __shfl_xor_sync(0xffffffffu, s2, 1);
        s1 += __shfl_xor_sync(0xffffffffu, s1, 2);
        s2 += __shfl_xor_sync(0xffffffffu, s2, 2);
        const float mean = s1 * (1.f / 192.f);
        const float rstd = rsqrtf(s2 * (1.f / 192.f) - mean * mean + 1e-5f);
        const bool wr = (e0 + e < E);
        #pragma unroll
        for (int g = 0; g < 12; g++) {
            int j0 = g * 16 + ts * 4;
            float4 q = *(const float4*)(B1 + (j0 & 63));
            float4 kv;
            if (j0 < 64)       kv = *(const float4*)(B1 + 64 + j0);
            else if (j0 < 128) kv = *(const float4*)(B2 + j0);
            else               kv = *(const float4*)(EProw + (j0 - 128));
            float4 p1 = *(const float4*)(B1 + 128 + j0);
            float4 p2 = *(const float4*)(B2 + 320 + j0);
            float4 eu = *(const float4*)(EProw + 64 + j0);
            float4 gv = __ldg((const float4*)(g1 + j0));
            float4 bv = __ldg((const float4*)(b1 + j0));
            float m[4];
            float x = (q.x * kv.x * INV - mean) * rstd * gv.x + bv.x;
            m[0] = (p1.x + p2.x + eu.x) / (1.f + __expf(-x));
            x = (q.y * kv.y * INV - mean) * rstd * gv.y + bv.y;
            m[1] = (p1.y + p2.y + eu.y) / (1.f + __expf(-x));
            x = (q.z * kv.z * INV - mean) * rstd * gv.z + bv.z;
            m[2] = (p1.z + p2.z + eu.z) / (1.f + __expf(-x));
            x = (q.w * kv.w * INV - mean) * rstd * gv.w + bv.w;
            m[3] = (p1.w + p2.w + eu.w) / (1.f + __expf(-x));
            if (wr) {
                float h0, l0, h1, l1, h2, l2, h3, l3;
                split2(m[0], h0, l0); split2(m[1], h1, l1);
                split2(m[2], h2, l2); split2(m[3], h3, l3);
                size_t base = (size_t)(e0 + e) * 192 + j0;
                *(uint32_t*)(g_MijHi + base)     = bf2(h0, h1);
                *(uint32_t*)(g_MijHi + base + 2) = bf2(h2, h3);
                *(uint32_t*)(g_MijLo + base)     = bf2(l0, l1);
                *(uint32_t*)(g_MijLo + base + 2) = bf2(l2, l3);
            }
        }
    }
}

// ================= E2: HMMA GEMM2 + LN2 + atomic scatter =================
// smem: sI1@0(512) sBM@512 sG2@1024 sB2@1536 | A_HI@4096(128x200) A_LO@55296
//       B_HI@106496 B_LO@157696 ; sMsg (f32 [128][132]) aliases @4096.
constexpr int E2_AHI = 4096, E2_ALO = 55296, E2_BHI = 106496, E2_BLO = 157696;
constexpr int E2_SMEM = 208896;

__global__ void __launch_bounds__(512, 1) e2_kernel(
    const void* __restrict__ idx1v,
    const float* __restrict__ bm,
    const float* __restrict__ g2, const float* __restrict__ b2,
    float* __restrict__ out, int E)
{
    extern __shared__ char smc[];
    const uint32_t smb = smem_u32(smc);
    int* sI1 = (int*)(smc);
    float* sBM = (float*)(smc + 512);
    float* sG2 = (float*)(smc + 1024);
    float* sB2 = (float*)(smc + 1536);
    float* sMsg = (float*)(smc + 4096);
    const int tid = threadIdx.x, w = tid >> 5, l = tid & 31;
    const int e0 = blockIdx.x * 128;

    if (tid < 128) {
        int e = e0 + tid, i1 = 0;
        if (e < E) i1 = g_idx64 ? (int)((const long long*)idx1v)[e] : ((const int*)idx1v)[e];
        sI1[tid] = i1;
        sBM[tid] = bm[tid]; sG2[tid] = g2[tid]; sB2[tid] = b2[tid];
    }
    // A: mij 128x192 bf16 hi/lo, stride 200
    #pragma unroll
    for (int i = tid; i < 128 * 96; i += 512) {
        int r = i / 96, kk = (i % 96) * 2;
        int e = e0 + r;
        uint32_t hi = 0, lo = 0;
        if (e < E) {
            size_t src = (size_t)e * 192 + kk;
            hi = *(const uint32_t*)(g_MijHi + src);
            lo = *(const uint32_t*)(g_MijLo + src);
        }
        uint32_t off = (uint32_t)(r * 200 + kk) * 2;
        *(uint32_t*)(smc + E2_AHI + off) = hi;
        *(uint32_t*)(smc + E2_ALO + off) = lo;
    }
    // B: WmT 128x192 bf16 hi/lo, stride 200
    #pragma unroll
    for (int i = tid; i < 128 * 96; i += 512) {
        int n = i / 96, kk = (i % 96) * 2;
        size_t src = (size_t)n * 192 + kk;
        uint32_t off = (uint32_t)(n * 200 + kk) * 2;
        *(uint32_t*)(smc + E2_BHI + off) = *(const uint32_t*)(g_WmHiT + src);
        *(uint32_t*)(smc + E2_BLO + off) = *(const uint32_t*)(g_WmLoT + src);
    }
    __syncthreads();

    // GEMM: warp w -> rows (w&7)*16, cols (w>>3)*64
    {
        const int r0 = (w & 7) * 16, cb = (w >> 3) * 64;
        float d[8][4];
        #pragma unroll
        for (int nt = 0; nt < 8; nt++)
            d[nt][0] = d[nt][1] = d[nt][2] = d[nt][3] = 0.f;
        const uint32_t aoffb = (uint32_t)((r0 + (l & 15)) * 200 + (l >> 4) * 8) * 2;
        const uint32_t boffb = (uint32_t)((cb + (l & 7)) * 200 + ((l >> 3) & 1) * 8) * 2;
        #pragma unroll
        for (int kt = 0; kt < 12; kt++) {
            uint32_t aH[4], aL[4];
            ldsm_x4(aH, smb + E2_AHI + aoffb + kt * 32);
            ldsm_x4(aL, smb + E2_ALO + aoffb + kt * 32);
            #pragma unroll
            for (int nt = 0; nt < 8; nt++) {
                uint32_t bH[2], bL[2];
                uint32_t bo = boffb + (uint32_t)(nt * 8 * 200) * 2 + kt * 32;
                ldsm_x2(bH, smb + E2_BHI + bo);
                ldsm_x2(bL, smb + E2_BLO + bo);
                mma_bf16(d[nt], aH, bH);
                mma_bf16(d[nt], aH, bL);
                mma_bf16(d[nt], aL, bH);
            }
        }
        __syncthreads();
        const int row = r0 + (l >> 2);
        #pragma unroll
        for (int nt = 0; nt < 8; nt++) {
            int col = cb + nt * 8 + 2 * (l & 3);
            sMsg[row * 132 + col]           = d[nt][0] + sBM[col];
            sMsg[row * 132 + col + 1]       = d[nt][1] + sBM[col + 1];
            sMsg[(row + 8) * 132 + col]     = d[nt][2] + sBM[col];
            sMsg[(row + 8) * 132 + col + 1] = d[nt][3] + sBM[col + 1];
        }
    }
    __syncthreads();

    // LN2 + atomic scatter (validated phase; 4 threads/row)
    {
        const int r = tid >> 2, ts = tid & 3, c0 = ts * 32;
        const float* row = sMsg + r * 132;
        float4 vv[8];
        float s1 = 0.f, s2 = 0.f;
        #pragma unroll
        for (int q = 0; q < 8; q++) {
            vv[q] = *(const float4*)(row + c0 + q * 4);
            s1 += vv[q].x + vv[q].y + vv[q].z + vv[q].w;
            s2 += vv[q].x * vv[q].x + vv[q].y * vv[q].y + vv[q].z * vv[q].z + vv[q].w * vv[q].w;
        }
        s1 += __shfl_xor_sync(0xffffffffu, s1, 1);
        s2 += __shfl_xor_sync(0xffffffffu, s2, 1);
        s1 += __shfl_xor_sync(0xffffffffu, s1, 2);
        s2 += __shfl_xor_sync(0xffffffffu, s2, 2);
        const float mean = s1 * (1.f / 128.f);
        const float rstd = rsqrtf(s2 * (1.f / 128.f) - mean * mean + 1e-5f);
        if (e0 + r < E) {
            float* dst = out + (size_t)sI1[r] * 128 + c0;
            #pragma unroll
            for (int q = 0; q < 8; q++) {
                const float* v = (const float*)&vv[q];
                #pragma unroll
                for (int c = 0; c < 4; c++) {
                    int j = c0 + q * 4 + c;
                    atomicAdd(dst + q * 4 + c,
                              (v[c] - mean) * rstd * sG2[j] + sB2[j]);
                }
            }
        }
    }
}

extern "C" void kernel_launch(void* const* d_in, const int* in_sizes, int n_in,
                              void* d_out, int out_size) {
    const float* nf = (const float*)d_in[0];
    const void* i1 = d_in[1];
    const void* i2 = d_in[2];
    const float* ef = (const float*)d_in[3];
    const float *WQ = (const float*)d_in[4],  *bQ = (const float*)d_in[5];
    const float *WK = (const float*)d_in[6],  *bK = (const float*)d_in[7];
    const float *WV = (const float*)d_in[8],  *bV = (const float*)d_in[9];
    const float *WE = (const float*)d_in[10], *bE = (const float*)d_in[11];
    const float *Wu = (const float*)d_in[12], *bu = (const float*)d_in[13];
    const float *Wm = (const float*)d_in[14], *bm = (const float*)d_in[15];
    const float *g1 = (const float*)d_in[16], *b1 = (const float*)d_in[17];
    const float *g2 = (const float*)d_in[18], *b2 = (const float*)d_in[19];
    const int N = in_sizes[0] / 128;
    const int E = in_sizes[3] / 64;

    cudaFuncSetAttribute(e1_kernel, cudaFuncAttributeMaxDynamicSharedMemorySize, E1_SMEM);
    cudaFuncSetAttribute(e2_kernel, cudaFuncAttributeMaxDynamicSharedMemorySize, E2_SMEM);

    zero_kernel<<<1024, 256>>>((float4*)d_out, out_size / 4);
    detect_kernel<<<1, 32>>>((const int*)i1, (const int*)i2, E);
    setup_kernel<<<160, 256>>>(WQ, bQ, WK, bK, WV, bV, WE, bE, Wu, bu);
    setup2_kernel<<<80, 256>>>(Wm);
    node_kernel<<<(N + 31) / 32, 256>>>(nf, N);
    e1_kernel<<<(E + 127) / 128, 512, E1_SMEM>>>(ef, i1, i2, g1, b1, E);
    e2_kernel<<<(E + 127) / 128, 512, E2_SMEM>>>(i1, bm, g2, b2, (float*)d_out, E);
}

// round 7
// speedup vs baseline: 3.4742x; 1.0337x over previous
#include <cuda_runtime.h>
#include <cuda_bf16.h>
#include <cstdint>
#include <cstddef>

#define MAXN 50000
typedef unsigned long long ull;

__device__ __forceinline__ void ffma2(ull &acc, ull a, ull b) {
    asm("fma.rn.f32x2 %0, %1, %2, %0;" : "+l"(acc) : "l"(a), "l"(b));
}
__device__ __forceinline__ ull pack2(float lo, float hi) {
    ull r; asm("mov.b64 %0, {%1, %2};" : "=l"(r) : "f"(lo), "f"(hi)); return r;
}
__device__ __forceinline__ float2 unpack2(ull v) {
    float lo, hi; asm("mov.b64 {%0, %1}, %2;" : "=f"(lo), "=f"(hi) : "l"(v));
    return make_float2(lo, hi);
}
__device__ __forceinline__ uint32_t smem_u32(const void* p) {
    uint32_t a; asm("{ .reg .u64 t; cvta.to.shared.u64 t, %1; cvt.u32.u64 %0, t; }"
                    : "=r"(a) : "l"(p));
    return a;
}
__device__ __forceinline__ void ldsm_x4(uint32_t* a, uint32_t addr) {
    asm volatile("ldmatrix.sync.aligned.m8n8.x4.shared.b16 {%0,%1,%2,%3}, [%4];"
                 : "=r"(a[0]), "=r"(a[1]), "=r"(a[2]), "=r"(a[3]) : "r"(addr));
}
__device__ __forceinline__ void mma_bf16(float* d, const uint32_t* a, const uint32_t* b) {
    asm volatile("mma.sync.aligned.m16n8k16.row.col.f32.bf16.bf16.f32 "
                 "{%0,%1,%2,%3},{%4,%5,%6,%7},{%8,%9},{%0,%1,%2,%3};"
                 : "+f"(d[0]), "+f"(d[1]), "+f"(d[2]), "+f"(d[3])
                 : "r"(a[0]), "r"(a[1]), "r"(a[2]), "r"(a[3]), "r"(b[0]), "r"(b[1]));
}
__device__ __forceinline__ uint32_t bf2(float a, float b) {
    __nv_bfloat162 h = __floats2bfloat162_rn(a, b);
    return *(uint32_t*)&h;
}
__device__ __forceinline__ void split2(float v, float& hi, float& lo) {
    __nv_bfloat16 h = __float2bfloat16_rn(v);
    hi = __bfloat162float(h);
    lo = v - hi;
}

// ---------------- device globals ----------------
__device__ __align__(16) float g_Wnode[128 * 512];
__device__ __align__(16) float g_Wedge[64 * 256];
__device__ float g_bnode[512];
__device__ float g_bedge[256];
__device__ __align__(16) float g_G[(size_t)MAXN * 512];
__device__ __align__(8) __nv_bfloat16 g_WeHiT[256 * 64];
__device__ __align__(8) __nv_bfloat16 g_WeLoT[256 * 64];
__device__ __align__(8) __nv_bfloat16 g_WmHiT[128 * 192];
__device__ __align__(8) __nv_bfloat16 g_WmLoT[128 * 192];
__device__ int g_idx64;

__global__ void zero_kernel(float4* out, int n4) {
    for (int i = blockIdx.x * blockDim.x + threadIdx.x; i < n4; i += gridDim.x * blockDim.x)
        out[i] = make_float4(0.f, 0.f, 0.f, 0.f);
}
__global__ void detect_kernel(const int* a, const int* b, int E) {
    if (threadIdx.x == 0) {
        int n = E < 64 ? E : 64, ok = 1;
        for (int i = 0; i < n; i++)
            if (a[2 * i + 1] != 0 || b[2 * i + 1] != 0) ok = 0;
        g_idx64 = ok;
    }
}

__global__ void setup_kernel(const float* __restrict__ WQ, const float* __restrict__ bQ,
                             const float* __restrict__ WK, const float* __restrict__ bK,
                             const float* __restrict__ WV, const float* __restrict__ bV,
                             const float* __restrict__ WE, const float* __restrict__ bE,
                             const float* __restrict__ Wu, const float* __restrict__ bu) {
    const int total = 65536 + 16384 + 512 + 256;
    for (int t = blockIdx.x * blockDim.x + threadIdx.x; t < total; t += gridDim.x * blockDim.x) {
        float v;
        if (t < 65536) {
            int d = t >> 9, c = t & 511;
            if (c < 64)       v = WQ[d * 64 + c];
            else if (c < 128) v = WK[d * 64 + (c - 64)];
            else {
                int j = (c < 320) ? (c - 128) : (c - 320);
                int rb = (c < 320) ? 0 : 64;
                float s = 0.f;
                #pragma unroll 8
                for (int k = 0; k < 64; k++) s += WV[d * 64 + k] * Wu[(rb + k) * 192 + j];
                v = s;
            }
            g_Wnode[t] = v;
        } else if (t < 81920) {
            int t2 = t - 65536, r = t2 >> 8, c = t2 & 255;
            if (c < 64) v = WE[r * 64 + c];
            else {
                int j = c - 64; float s = 0.f;
                #pragma unroll 8
                for (int k = 0; k < 64; k++) s += WE[r * 64 + k] * Wu[(128 + k) * 192 + j];
                v = s;
            }
            g_Wedge[t2] = v;
        } else if (t < 82432) {
            int i = t - 81920;
            if (i < 64)       v = bQ[i];
            else if (i < 128) v = bK[i - 64];
            else {
                int j = (i < 320) ? (i - 128) : (i - 320);
                int rb = (i < 320) ? 0 : 64;
                float s = 0.f;
                #pragma unroll 8
                for (int k = 0; k < 64; k++) s += bV[k] * Wu[(rb + k) * 192 + j];
                v = s;
            }
            g_bnode[i] = v;
        } else {
            int i = t - 82432;
            if (i < 64) v = bE[i];
            else {
                int j = i - 64;
                float s = bu[j];
                #pragma unroll 8
                for (int k = 0; k < 64; k++) s += bE[k] * Wu[(128 + k) * 192 + j];
                v = s;
            }
            g_bedge[i] = v;
        }
    }
}

__global__ void setup2_kernel(const float* __restrict__ Wm) {
    const int total = 16384 + 24576;
    for (int t = blockIdx.x * blockDim.x + threadIdx.x; t < total; t += gridDim.x * blockDim.x) {
        if (t < 16384) {
            int n = t >> 6, k = t & 63;
            float v = g_Wedge[k * 256 + n], hi, lo;
            split2(v, hi, lo);
            g_WeHiT[t] = __float2bfloat16_rn(hi);
            g_WeLoT[t] = __float2bfloat16_rn(lo);
        } else {
            int t2 = t - 16384, n = t2 / 192, k = t2 % 192;
            float v = Wm[k * 128 + n], hi, lo;
            split2(v, hi, lo);
            g_WmHiT[t2] = __float2bfloat16_rn(hi);
            g_WmLoT[t2] = __float2bfloat16_rn(lo);
        }
    }
}

// node kernel (known-good)
__global__ void __launch_bounds__(256) node_kernel(const float* __restrict__ nf, int N) {
    __shared__ float sA[32 * 260];
    const int tid = threadIdx.x, tile = blockIdx.x * 32;
    #pragma unroll
    for (int i = tid; i < 32 * 32; i += 256) {
        int r = i >> 5, c4 = (i & 31) << 2, n = tile + r;
        float4 v = make_float4(0.f, 0.f, 0.f, 0.f);
        if (n < N) v = *(const float4*)(nf + (size_t)n * 128 + c4);
        float2* dst = (float2*)(sA + r * 260 + 2 * c4);
        dst[0] = make_float2(v.x, v.x); dst[1] = make_float2(v.y, v.y);
        dst[2] = make_float2(v.z, v.z); dst[3] = make_float2(v.w, v.w);
    }
    __syncthreads();
    const int cg = tid & 63, rg = tid >> 6, c0 = cg * 8, r0 = rg * 8;
    ull acc[8][4];
    #pragma unroll
    for (int p = 0; p < 4; p++) {
        ull bb = pack2(g_bnode[c0 + 2 * p], g_bnode[c0 + 2 * p + 1]);
        #pragma unroll
        for (int r = 0; r < 8; r++) acc[r][p] = bb;
    }
    #pragma unroll 4
    for (int k = 0; k < 128; k++) {
        ulonglong2 w0 = *(const ulonglong2*)(g_Wnode + k * 512 + c0);
        ulonglong2 w1 = *(const ulonglong2*)(g_Wnode + k * 512 + c0 + 4);
        #pragma unroll
        for (int r = 0; r < 8; r++) {
            ull a2 = *(const ull*)(sA + (r0 + r) * 260 + 2 * k);
            ffma2(acc[r][0], a2, w0.x); ffma2(acc[r][1], a2, w0.y);
            ffma2(acc[r][2], a2, w1.x); ffma2(acc[r][3], a2, w1.y);
        }
    }
    #pragma unroll
    for (int r = 0; r < 8; r++) {
        int n = tile + r0 + r;
        if (n < N) {
            float2 p0 = unpack2(acc[r][0]), p1 = unpack2(acc[r][1]);
            float2 p2 = unpack2(acc[r][2]), p3 = unpack2(acc[r][3]);
            float4* dst = (float4*)(g_G + (size_t)n * 512 + c0);
            dst[0] = make_float4(p0.x, p0.y, p1.x, p1.y);
            dst[1] = make_float4(p2.x, p2.y, p3.x, p3.y);
        }
    }
}

// ================= fused edge kernel =================
// phase1: A_HI@4096 A_LO@22528 (128x72) | B_HI@40960 B_LO@77824 (256x72)
// phase2: sEPU f32[128][260] @75776 (aliases B tail + beyond; write after sync)
// phase4: M_HI@4096 M_LO@55296 (128x200) | W_HI@106496 W_LO@157696 (128x200)
// phase5: sMsg f32[128][132] @106496 (aliases W after GEMM2)
constexpr int F_AHI = 4096, F_ALO = 22528, F_BHI = 40960, F_BLO = 77824;
constexpr int F_SEPU = 75776;
constexpr int F_MHI = 4096, F_MLO = 55296, F_WHI = 106496, F_WLO = 157696;
constexpr int F_MSG = 106496;
constexpr int F_SMEM = 208896;

__global__ void __launch_bounds__(512, 1) edge_kernel(
    const float* __restrict__ edge_fea,
    const void* __restrict__ idx1v, const void* __restrict__ idx2v,
    const float* __restrict__ g1, const float* __restrict__ b1,
    const float* __restrict__ bm,
    const float* __restrict__ g2, const float* __restrict__ b2,
    float* __restrict__ out, int E)
{
    extern __shared__ char smc[];
    const uint32_t smb = smem_u32(smc);
    int* sI1 = (int*)(smc);
    int* sI2 = (int*)(smc + 512);
    float* sBM = (float*)(smc + 1024);
    float* sG2 = (float*)(smc + 1536);
    float* sB2 = (float*)(smc + 2048);
    float* sEPU = (float*)(smc + F_SEPU);
    float* sMsg = (float*)(smc + F_MSG);
    const int tid = threadIdx.x, w = tid >> 5, l = tid & 31;
    const int e0 = blockIdx.x * 128;

    if (tid < 128) {
        int e = e0 + tid, i1 = 0, i2 = 0;
        if (e < E) {
            if (g_idx64) {
                i1 = (int)((const long long*)idx1v)[e];
                i2 = (int)((const long long*)idx2v)[e];
            } else {
                i1 = ((const int*)idx1v)[e];
                i2 = ((const int*)idx2v)[e];
            }
        }
        sI1[tid] = i1; sI2[tid] = i2;
        sBM[tid] = bm[tid]; sG2[tid] = g2[tid]; sB2[tid] = b2[tid];
    }
    // A: edge_fea 128x64 -> bf16 hi/lo, stride 72
    #pragma unroll
    for (int i = tid; i < 128 * 16; i += 512) {
        int r = i >> 4, c4 = (i & 15) << 2, e = e0 + r;
        float4 v = make_float4(0.f, 0.f, 0.f, 0.f);
        if (e < E) v = *(const float4*)(edge_fea + (size_t)e * 64 + c4);
        float h0, l0, h1, l1, h2, l2, h3, l3;
        split2(v.x, h0, l0); split2(v.y, h1, l1); split2(v.z, h2, l2); split2(v.w, h3, l3);
        uint32_t off = (uint32_t)(r * 72 + c4) * 2;
        *(uint32_t*)(smc + F_AHI + off) = bf2(h0, h1);
        *(uint32_t*)(smc + F_AHI + off + 4) = bf2(h2, h3);
        *(uint32_t*)(smc + F_ALO + off) = bf2(l0, l1);
        *(uint32_t*)(smc + F_ALO + off + 4) = bf2(l2, l3);
    }
    // B: WeT 256x64 bf16 (pre-split), stride 72
    #pragma unroll
    for (int i = tid; i < 256 * 32; i += 512) {
        int n = i >> 5, kk = (i & 31) * 2;
        uint32_t off = (uint32_t)(n * 72 + kk) * 2;
        *(uint32_t*)(smc + F_BHI + off) = *(const uint32_t*)(g_WeHiT + n * 64 + kk);
        *(uint32_t*)(smc + F_BLO + off) = *(const uint32_t*)(g_WeLoT + n * 64 + kk);
    }
    __syncthreads();

    // ---- GEMM1: warp -> rows (w&7)*16, cols (w>>3)*128; x4 B ldsm ----
    {
        const int r0 = (w & 7) * 16, cb = (w >> 3) * 128;
        float d[16][4];
        #pragma unroll
        for (int nt = 0; nt < 16; nt++)
            d[nt][0] = d[nt][1] = d[nt][2] = d[nt][3] = 0.f;
        const uint32_t aoffb = (uint32_t)((r0 + (l & 15)) * 72 + (l >> 4) * 8) * 2;
        const int nrow = (l & 7) + ((l >> 4) << 3);
        const uint32_t boffb = (uint32_t)((cb + nrow) * 72 + ((l >> 3) & 1) * 8) * 2;
        #pragma unroll
        for (int kt = 0; kt < 4; kt++) {
            uint32_t aH[4], aL[4];
            ldsm_x4(aH, smb + F_AHI + aoffb + kt * 32);
            ldsm_x4(aL, smb + F_ALO + aoffb + kt * 32);
            #pragma unroll
            for (int nt = 0; nt < 8; nt++) {
                uint32_t bH[4], bL[4];
                uint32_t bo = boffb + (uint32_t)(nt * 16 * 72) * 2 + kt * 32;
                ldsm_x4(bH, smb + F_BHI + bo);
                ldsm_x4(bL, smb + F_BLO + bo);
                mma_bf16(d[2 * nt],     aH, bH);     mma_bf16(d[2 * nt],     aH, bL);
                mma_bf16(d[2 * nt],     aL, bH);
                mma_bf16(d[2 * nt + 1], aH, bH + 2); mma_bf16(d[2 * nt + 1], aH, bL + 2);
                mma_bf16(d[2 * nt + 1], aL, bH + 2);
            }
        }
        __syncthreads();   // all tile reads done; safe to write sEPU
        const int row = r0 + (l >> 2);
        #pragma unroll
        for (int nt = 0; nt < 16; nt++) {
            int col = cb + nt * 8 + 2 * (l & 3);
            sEPU[row * 260 + col]           = d[nt][0] + g_bedge[col];
            sEPU[row * 260 + col + 1]       = d[nt][1] + g_bedge[col + 1];
            sEPU[(row + 8) * 260 + col]     = d[nt][2] + g_bedge[col];
            sEPU[(row + 8) * 260 + col + 1] = d[nt][3] + g_bedge[col + 1];
        }
    }
    __syncthreads();

    // ---- attention + LN1 + gate -> mij in registers ----
    float m[12][4];
    {
        const int e = tid >> 2, ts = tid & 3;
        const float* B1 = g_G + (size_t)sI1[e] * 512;
        const float* B2 = g_G + (size_t)sI2[e] * 512;
        const float* EProw = sEPU + e * 260;
        const float INV = 0.07216878364870323f;  // 1/sqrt(192)
        float s1 = 0.f, s2 = 0.f;
        #pragma unroll
        for (int g = 0; g < 12; g++) {
            int j0 = g * 16 + ts * 4;
            float4 q = *(const float4*)(B1 + (j0 & 63));
            float4 kv;
            if (j0 < 64)       kv = *(const float4*)(B1 + 64 + j0);
            else if (j0 < 128) kv = *(const float4*)(B2 + j0);
            else               kv = *(const float4*)(EProw + (j0 - 128));
            float ax = q.x * kv.x * INV, ay = q.y * kv.y * INV;
            float az = q.z * kv.z * INV, aw = q.w * kv.w * INV;
            s1 += ax + ay + az + aw;
            s2 += ax * ax + ay * ay + az * az + aw * aw;
        }
        s1 += __shfl_xor_sync(0xffffffffu, s1, 1);
        s2 += __shfl_xor_sync(0xffffffffu, s2, 1);
        s1 += __shfl_xor_sync(0xffffffffu, s1, 2);
        s2 += __shfl_xor_sync(0xffffffffu, s2, 2);
        const float mean = s1 * (1.f / 192.f);
        const float rstd = rsqrtf(s2 * (1.f / 192.f) - mean * mean + 1e-5f);
        #pragma unroll
        for (int g = 0; g < 12; g++) {
            int j0 = g * 16 + ts * 4;
            float4 q = *(const float4*)(B1 + (j0 & 63));
            float4 kv;
            if (j0 < 64)       kv = *(const float4*)(B1 + 64 + j0);
            else if (j0 < 128) kv = *(const float4*)(B2 + j0);
            else               kv = *(const float4*)(EProw + (j0 - 128));
            float4 p1 = *(const float4*)(B1 + 128 + j0);
            float4 p2 = *(const float4*)(B2 + 320 + j0);
            float4 eu = *(const float4*)(EProw + 64 + j0);
            float4 gv = __ldg((const float4*)(g1 + j0));
            float4 bv = __ldg((const float4*)(b1 + j0));
            float x = (q.x * kv.x * INV - mean) * rstd * gv.x + bv.x;
            m[g][0] = (p1.x + p2.x + eu.x) / (1.f + __expf(-x));
            x = (q.y * kv.y * INV - mean) * rstd * gv.y + bv.y;
            m[g][1] = (p1.y + p2.y + eu.y) / (1.f + __expf(-x));
            x = (q.z * kv.z * INV - mean) * rstd * gv.z + bv.z;
            m[g][2] = (p1.z + p2.z + eu.z) / (1.f + __expf(-x));
            x = (q.w * kv.w * INV - mean) * rstd * gv.w + bv.w;
            m[g][3] = (p1.w + p2.w + eu.w) / (1.f + __expf(-x));
        }
    }
    __syncthreads();   // sEPU reads done; alias M and W over it

    // write mij bf16 hi/lo to smem (stride 200) + load Wm tiles
    {
        const int e = tid >> 2, ts = tid & 3;
        #pragma unroll
        for (int g = 0; g < 12; g++) {
            int j0 = g * 16 + ts * 4;
            float h0, l0, h1, l1, h2, l2, h3, l3;
            split2(m[g][0], h0, l0); split2(m[g][1], h1, l1);
            split2(m[g][2], h2, l2); split2(m[g][3], h3, l3);
            uint32_t off = (uint32_t)(e * 200 + j0) * 2;
            *(uint32_t*)(smc + F_MHI + off)     = bf2(h0, h1);
            *(uint32_t*)(smc + F_MHI + off + 4) = bf2(h2, h3);
            *(uint32_t*)(smc + F_MLO + off)     = bf2(l0, l1);
            *(uint32_t*)(smc + F_MLO + off + 4) = bf2(l2, l3);
        }
    }
    #pragma unroll
    for (int i = tid; i < 128 * 96; i += 512) {
        int n = i / 96, kk = (i % 96) * 2;
        size_t src = (size_t)n * 192 + kk;
        uint32_t off = (uint32_t)(n * 200 + kk) * 2;
        *(uint32_t*)(smc + F_WHI + off) = *(const uint32_t*)(g_WmHiT + src);
        *(uint32_t*)(smc + F_WLO + off) = *(const uint32_t*)(g_WmLoT + src);
    }
    __syncthreads();

    // ---- GEMM2: warp -> rows (w&7)*16, cols (w>>3)*64; x4 B ldsm ----
    {
        const int r0 = (w & 7) * 16, cb = (w >> 3) * 64;
        float d[8][4];
        #pragma unroll
        for (int nt = 0; nt < 8; nt++)
            d[nt][0] = d[nt][1] = d[nt][2] = d[nt][3] = 0.f;
        const uint32_t aoffb = (uint32_t)((r0 + (l & 15)) * 200 + (l >> 4) * 8) * 2;
        const int nrow = (l & 7) + ((l >> 4) << 3);
        const uint32_t boffb = (uint32_t)((cb + nrow) * 200 + ((l >> 3) & 1) * 8) * 2;
        #pragma unroll
        for (int kt = 0; kt < 12; kt++) {
            uint32_t aH[4], aL[4];
            ldsm_x4(aH, smb + F_MHI + aoffb + kt * 32);
            ldsm_x4(aL, smb + F_MLO + aoffb + kt * 32);
            #pragma unroll
            for (int nt = 0; nt < 4; nt++) {
                uint32_t bH[4], bL[4];
                uint32_t bo = boffb + (uint32_t)(nt * 16 * 200) * 2 + kt * 32;
                ldsm_x4(bH, smb + F_WHI + bo);
                ldsm_x4(bL, smb + F_WLO + bo);
                mma_bf16(d[2 * nt],     aH, bH);     mma_bf16(d[2 * nt],     aH, bL);
                mma_bf16(d[2 * nt],     aL, bH);
                mma_bf16(d[2 * nt + 1], aH, bH + 2); mma_bf16(d[2 * nt + 1], aH, bL + 2);
                mma_bf16(d[2 * nt + 1], aL, bH + 2);
            }
        }
        __syncthreads();   // W reads done; safe to write sMsg over W
        const int row = r0 + (l >> 2);
        #pragma unroll
        for (int nt = 0; nt < 8; nt++) {
            int col = cb + nt * 8 + 2 * (l & 3);
            sMsg[row * 132 + col]           = d[nt][0] + sBM[col];
            sMsg[row * 132 + col + 1]       = d[nt][1] + sBM[col + 1];
            sMsg[(row + 8) * 132 + col]     = d[nt][2] + sBM[col];
            sMsg[(row + 8) * 132 + col + 1] = d[nt][3] + sBM[col + 1];
        }
    }
    __syncthreads();

    // ---- LN2 + atomic scatter ----
    {
        const int r = tid >> 2, ts = tid & 3, c0 = ts * 32;
        const float* row = sMsg + r * 132;
        float4 vv[8];
        float s1 = 0.f, s2 = 0.f;
        #pragma unroll
        for (int q = 0; q < 8; q++) {
            vv[q] = *(const float4*)(row + c0 + q * 4);
            s1 += vv[q].x + vv[q].y + vv[q].z + vv[q].w;
            s2 += vv[q].x * vv[q].x + vv[q].y * vv[q].y + vv[q].z * vv[q].z + vv[q].w * vv[q].w;
        }
        s1 += __shfl_xor_sync(0xffffffffu, s1, 1);
        s2 += __shfl_xor_sync(0xffffffffu, s2, 1);
        s1 += __shfl_xor_sync(0xffffffffu, s1, 2);
        s2 += __shfl_xor_sync(0xffffffffu, s2, 2);
        const float mean = s1 * (1.f / 128.f);
        const float rstd = rsqrtf(s2 * (1.f / 128.f) - mean * mean + 1e-5f);
        if (e0 + r < E) {
            float* dst = out + (size_t)sI1[r] * 128 + c0;
            #pragma unroll
            for (int q = 0; q < 8; q++) {
                const float* v = (const float*)&vv[q];
                #pragma unroll
                for (int c = 0; c < 4; c++) {
                    int j = c0 + q * 4 + c;
                    atomicAdd(dst + q * 4 + c,
                              (v[c] - mean) * rstd * sG2[j] + sB2[j]);
                }
            }
        }
    }
}

extern "C" void kernel_launch(void* const* d_in, const int* in_sizes, int n_in,
                              void* d_out, int out_size) {
    const float* nf = (const float*)d_in[0];
    const void* i1 = d_in[1];
    const void* i2 = d_in[2];
    const float* ef = (const float*)d_in[3];
    const float *WQ = (const float*)d_in[4],  *bQ = (const float*)d_in[5];
    const float *WK = (const float*)d_in[6],  *bK = (const float*)d_in[7];
    const float *WV = (const float*)d_in[8],  *bV = (const float*)d_in[9];
    const float *WE = (const float*)d_in[10], *bE = (const float*)d_in[11];
    const float *Wu = (const float*)d_in[12], *bu = (const float*)d_in[13];
    const float *Wm = (const float*)d_in[14], *bm = (const float*)d_in[15];
    const float *g1 = (const float*)d_in[16], *b1 = (const float*)d_in[17];
    const float *g2 = (const float*)d_in[18], *b2 = (const float*)d_in[19];
    const int N = in_sizes[0] / 128;
    const int E = in_sizes[3] / 64;

    cudaFuncSetAttribute(edge_kernel, cudaFuncAttributeMaxDynamicSharedMemorySize, F_SMEM);

    zero_kernel<<<1024, 256>>>((float4*)d_out, out_size / 4);
    detect_kernel<<<1, 32>>>((const int*)i1, (const int*)i2, E);
    setup_kernel<<<160, 256>>>(WQ, bQ, WK, bK, WV, bV, WE, bE, Wu, bu);
    setup2_kernel<<<80, 256>>>(Wm);
    node_kernel<<<(N + 31) / 32, 256>>>(nf, N);
    edge_kernel<<<(E + 127) / 128, 512, F_SMEM>>>(
        ef, i1, i2, g1, b1, bm, g2, b2, (float*)d_out, E);
}

// round 8
// speedup vs baseline: 4.6125x; 1.3277x over previous
#include <cuda_runtime.h>
#include <cuda_bf16.h>
#include <cuda_fp16.h>
#include <cstdint>
#include <cstddef>

#define MAXN 50000
typedef unsigned long long ull;

__device__ __forceinline__ void ffma2(ull &acc, ull a, ull b) {
    asm("fma.rn.f32x2 %0, %1, %2, %0;" : "+l"(acc) : "l"(a), "l"(b));
}
__device__ __forceinline__ ull pack2(float lo, float hi) {
    ull r; asm("mov.b64 %0, {%1, %2};" : "=l"(r) : "f"(lo), "f"(hi)); return r;
}
__device__ __forceinline__ float2 unpack2(ull v) {
    float lo, hi; asm("mov.b64 {%0, %1}, %2;" : "=f"(lo), "=f"(hi) : "l"(v));
    return make_float2(lo, hi);
}
__device__ __forceinline__ uint32_t smem_u32(const void* p) {
    uint32_t a; asm("{ .reg .u64 t; cvta.to.shared.u64 t, %1; cvt.u32.u64 %0, t; }"
                    : "=r"(a) : "l"(p));
    return a;
}
__device__ __forceinline__ void ldsm_x4(uint32_t* a, uint32_t addr) {
    asm volatile("ldmatrix.sync.aligned.m8n8.x4.shared.b16 {%0,%1,%2,%3}, [%4];"
                 : "=r"(a[0]), "=r"(a[1]), "=r"(a[2]), "=r"(a[3]) : "r"(addr));
}
__device__ __forceinline__ void mma_f16(float* d, const uint32_t* a, const uint32_t* b) {
    asm volatile("mma.sync.aligned.m16n8k16.row.col.f32.f16.f16.f32 "
                 "{%0,%1,%2,%3},{%4,%5,%6,%7},{%8,%9},{%0,%1,%2,%3};"
                 : "+f"(d[0]), "+f"(d[1]), "+f"(d[2]), "+f"(d[3])
                 : "r"(a[0]), "r"(a[1]), "r"(a[2]), "r"(a[3]), "r"(b[0]), "r"(b[1]));
}
__device__ __forceinline__ uint32_t h2(float a, float b) {
    __half2 h = __floats2half2_rn(a, b);
    return *(uint32_t*)&h;
}

// ---------------- device globals ----------------
__device__ __align__(16) float g_Wnode[128 * 512];
__device__ __align__(16) float g_Wedge[64 * 256];
__device__ float g_bnode[512];
__device__ float g_bedge[256];
__device__ __align__(16) float g_G[(size_t)MAXN * 512];
__device__ __align__(8) __half g_WeT[256 * 64];    // [n][k] fp16
__device__ __align__(8) __half g_WmT[128 * 192];   // [n][k] fp16
__device__ int g_idx64;

__global__ void zero_kernel(float4* out, int n4) {
    for (int i = blockIdx.x * blockDim.x + threadIdx.x; i < n4; i += gridDim.x * blockDim.x)
        out[i] = make_float4(0.f, 0.f, 0.f, 0.f);
}
__global__ void detect_kernel(const int* a, const int* b, int E) {
    if (threadIdx.x == 0) {
        int n = E < 64 ? E : 64, ok = 1;
        for (int i = 0; i < n; i++)
            if (a[2 * i + 1] != 0 || b[2 * i + 1] != 0) ok = 0;
        g_idx64 = ok;
    }
}

__global__ void setup_kernel(const float* __restrict__ WQ, const float* __restrict__ bQ,
                             const float* __restrict__ WK, const float* __restrict__ bK,
                             const float* __restrict__ WV, const float* __restrict__ bV,
                             const float* __restrict__ WE, const float* __restrict__ bE,
                             const float* __restrict__ Wu, const float* __restrict__ bu) {
    const int total = 65536 + 16384 + 512 + 256;
    for (int t = blockIdx.x * blockDim.x + threadIdx.x; t < total; t += gridDim.x * blockDim.x) {
        float v;
        if (t < 65536) {
            int d = t >> 9, c = t & 511;
            if (c < 64)       v = WQ[d * 64 + c];
            else if (c < 128) v = WK[d * 64 + (c - 64)];
            else {
                int j = (c < 320) ? (c - 128) : (c - 320);
                int rb = (c < 320) ? 0 : 64;
                float s = 0.f;
                #pragma unroll 8
                for (int k = 0; k < 64; k++) s += WV[d * 64 + k] * Wu[(rb + k) * 192 + j];
                v = s;
            }
            g_Wnode[t] = v;
        } else if (t < 81920) {
            int t2 = t - 65536, r = t2 >> 8, c = t2 & 255;
            if (c < 64) v = WE[r * 64 + c];
            else {
                int j = c - 64; float s = 0.f;
                #pragma unroll 8
                for (int k = 0; k < 64; k++) s += WE[r * 64 + k] * Wu[(128 + k) * 192 + j];
                v = s;
            }
            g_Wedge[t2] = v;
        } else if (t < 82432) {
            int i = t - 81920;
            if (i < 64)       v = bQ[i];
            else if (i < 128) v = bK[i - 64];
            else {
                int j = (i < 320) ? (i - 128) : (i - 320);
                int rb = (i < 320) ? 0 : 64;
                float s = 0.f;
                #pragma unroll 8
                for (int k = 0; k < 64; k++) s += bV[k] * Wu[(rb + k) * 192 + j];
                v = s;
            }
            g_bnode[i] = v;
        } else {
            int i = t - 82432;
            if (i < 64) v = bE[i];
            else {
                int j = i - 64;
                float s = bu[j];
                #pragma unroll 8
                for (int k = 0; k < 64; k++) s += bE[k] * Wu[(128 + k) * 192 + j];
                v = s;
            }
            g_bedge[i] = v;
        }
    }
}

__global__ void setup2_kernel(const float* __restrict__ Wm) {
    const int total = 16384 + 24576;
    for (int t = blockIdx.x * blockDim.x + threadIdx.x; t < total; t += gridDim.x * blockDim.x) {
        if (t < 16384) {
            int n = t >> 6, k = t & 63;
            g_WeT[t] = __float2half_rn(g_Wedge[k * 256 + n]);
        } else {
            int t2 = t - 16384, n = t2 / 192, k = t2 % 192;
            g_WmT[t2] = __float2half_rn(Wm[k * 128 + n]);
        }
    }
}

// node kernel (known-good)
__global__ void __launch_bounds__(256) node_kernel(const float* __restrict__ nf, int N) {
    __shared__ float sA[32 * 260];
    const int tid = threadIdx.x, tile = blockIdx.x * 32;
    #pragma unroll
    for (int i = tid; i < 32 * 32; i += 256) {
        int r = i >> 5, c4 = (i & 31) << 2, n = tile + r;
        float4 v = make_float4(0.f, 0.f, 0.f, 0.f);
        if (n < N) v = *(const float4*)(nf + (size_t)n * 128 + c4);
        float2* dst = (float2*)(sA + r * 260 + 2 * c4);
        dst[0] = make_float2(v.x, v.x); dst[1] = make_float2(v.y, v.y);
        dst[2] = make_float2(v.z, v.z); dst[3] = make_float2(v.w, v.w);
    }
    __syncthreads();
    const int cg = tid & 63, rg = tid >> 6, c0 = cg * 8, r0 = rg * 8;
    ull acc[8][4];
    #pragma unroll
    for (int p = 0; p < 4; p++) {
        ull bb = pack2(g_bnode[c0 + 2 * p], g_bnode[c0 + 2 * p + 1]);
        #pragma unroll
        for (int r = 0; r < 8; r++) acc[r][p] = bb;
    }
    #pragma unroll 4
    for (int k = 0; k < 128; k++) {
        ulonglong2 w0 = *(const ulonglong2*)(g_Wnode + k * 512 + c0);
        ulonglong2 w1 = *(const ulonglong2*)(g_Wnode + k * 512 + c0 + 4);
        #pragma unroll
        for (int r = 0; r < 8; r++) {
            ull a2 = *(const ull*)(sA + (r0 + r) * 260 + 2 * k);
            ffma2(acc[r][0], a2, w0.x); ffma2(acc[r][1], a2, w0.y);
            ffma2(acc[r][2], a2, w1.x); ffma2(acc[r][3], a2, w1.y);
        }
    }
    #pragma unroll
    for (int r = 0; r < 8; r++) {
        int n = tile + r0 + r;
        if (n < N) {
            float2 p0 = unpack2(acc[r][0]), p1 = unpack2(acc[r][1]);
            float2 p2 = unpack2(acc[r][2]), p3 = unpack2(acc[r][3]);
            float4* dst = (float4*)(g_G + (size_t)n * 512 + c0);
            dst[0] = make_float4(p0.x, p0.y, p1.x, p1.y);
            dst[1] = make_float4(p2.x, p2.y, p3.x, p3.y);
        }
    }
}

// ================= fused edge kernel (TE=64, fp16, occ 2) =================
// base scalars @0..3584; A@4096(64x72 h) B@13312(256x72 h)
// sEPU f32[64][260] @4096 (aliases A,B after GEMM1)
// M@4096(64x200 h)  W@29696(128x200 h)  sMsg f32[64][132] @29696 (aliases W)
constexpr int F_A = 4096, F_B = 13312;
constexpr int F_EPU = 4096;
constexpr int F_M = 4096, F_W = 29696, F_MSG = 29696;
constexpr int F_SMEM = 81920;

__global__ void __launch_bounds__(256, 2) edge_kernel(
    const float* __restrict__ edge_fea,
    const void* __restrict__ idx1v, const void* __restrict__ idx2v,
    const float* __restrict__ g1, const float* __restrict__ b1,
    const float* __restrict__ bm,
    const float* __restrict__ g2, const float* __restrict__ b2,
    float* __restrict__ out, int E)
{
    extern __shared__ char smc[];
    const uint32_t smb = smem_u32(smc);
    int* sI1 = (int*)(smc);
    int* sI2 = (int*)(smc + 256);
    float* sBM = (float*)(smc + 512);
    float* sG2 = (float*)(smc + 1024);
    float* sB2 = (float*)(smc + 1536);
    float* sG1 = (float*)(smc + 2048);
    float* sB1 = (float*)(smc + 2816);
    float* sEPU = (float*)(smc + F_EPU);
    float* sMsg = (float*)(smc + F_MSG);
    const int tid = threadIdx.x, w = tid >> 5, l = tid & 31;
    const int e0 = blockIdx.x * 64;

    if (tid < 64) {
        int e = e0 + tid, i1 = 0, i2 = 0;
        if (e < E) {
            if (g_idx64) {
                i1 = (int)((const long long*)idx1v)[e];
                i2 = (int)((const long long*)idx2v)[e];
            } else {
                i1 = ((const int*)idx1v)[e];
                i2 = ((const int*)idx2v)[e];
            }
        }
        sI1[tid] = i1; sI2[tid] = i2;
    }
    if (tid < 128) { sBM[tid] = bm[tid]; sG2[tid] = g2[tid]; sB2[tid] = b2[tid]; }
    if (tid < 192) { sG1[tid] = g1[tid]; sB1[tid] = b1[tid]; }
    // A: edge_fea 64x64 -> fp16, stride 72
    #pragma unroll
    for (int i = tid; i < 64 * 16; i += 256) {
        int r = i >> 4, c4 = (i & 15) << 2, e = e0 + r;
        float4 v = make_float4(0.f, 0.f, 0.f, 0.f);
        if (e < E) v = *(const float4*)(edge_fea + (size_t)e * 64 + c4);
        uint32_t off = (uint32_t)(r * 72 + c4) * 2;
        *(uint32_t*)(smc + F_A + off)     = h2(v.x, v.y);
        *(uint32_t*)(smc + F_A + off + 4) = h2(v.z, v.w);
    }
    // B: WeT 256x64 fp16, stride 72
    #pragma unroll
    for (int i = tid; i < 256 * 32; i += 256) {
        int n = i >> 5, kk = (i & 31) * 2;
        uint32_t off = (uint32_t)(n * 72 + kk) * 2;
        *(uint32_t*)(smc + F_B + off) = *(const uint32_t*)(g_WeT + n * 64 + kk);
    }
    __syncthreads();

    // ---- GEMM1: warp -> rows (w&3)*16, cols (w>>2)*128 ----
    {
        const int r0 = (w & 3) * 16, cb = (w >> 2) * 128;
        float d[16][4];
        #pragma unroll
        for (int nt = 0; nt < 16; nt++)
            d[nt][0] = d[nt][1] = d[nt][2] = d[nt][3] = 0.f;
        const uint32_t aoffb = (uint32_t)((r0 + (l & 15)) * 72 + (l >> 4) * 8) * 2;
        const int nrow = (l & 7) + ((l >> 4) << 3);
        const uint32_t boffb = (uint32_t)((cb + nrow) * 72 + ((l >> 3) & 1) * 8) * 2;
        #pragma unroll
        for (int kt = 0; kt < 4; kt++) {
            uint32_t aF[4];
            ldsm_x4(aF, smb + F_A + aoffb + kt * 32);
            #pragma unroll
            for (int nt = 0; nt < 8; nt++) {
                uint32_t bF[4];
                ldsm_x4(bF, smb + F_B + boffb + (uint32_t)(nt * 16 * 72) * 2 + kt * 32);
                mma_f16(d[2 * nt],     aF, bF);
                mma_f16(d[2 * nt + 1], aF, bF + 2);
            }
        }
        __syncthreads();   // tile reads done; safe to write sEPU over A/B
        const int row = r0 + (l >> 2);
        #pragma unroll
        for (int nt = 0; nt < 16; nt++) {
            int col = cb + nt * 8 + 2 * (l & 3);
            sEPU[row * 260 + col]           = d[nt][0] + g_bedge[col];
            sEPU[row * 260 + col + 1]       = d[nt][1] + g_bedge[col + 1];
            sEPU[(row + 8) * 260 + col]     = d[nt][2] + g_bedge[col];
            sEPU[(row + 8) * 260 + col + 1] = d[nt][3] + g_bedge[col + 1];
        }
    }
    __syncthreads();

    // ---- attention + LN1 + gate; aval kept in registers ----
    float m[12][4];
    {
        const int e = tid >> 2, ts = tid & 3;
        const float* B1 = g_G + (size_t)sI1[e] * 512;
        const float* B2 = g_G + (size_t)sI2[e] * 512;
        const float* EProw = sEPU + e * 260;
        const float INV = 0.07216878364870323f;  // 1/sqrt(192)
        float s1 = 0.f, s2 = 0.f;
        #pragma unroll
        for (int g = 0; g < 12; g++) {
            int j0 = g * 16 + ts * 4;
            float4 q = *(const float4*)(B1 + (j0 & 63));
            float4 kv;
            if (j0 < 64)       kv = *(const float4*)(B1 + 64 + j0);
            else if (j0 < 128) kv = *(const float4*)(B2 + j0);
            else               kv = *(const float4*)(EProw + (j0 - 128));
            m[g][0] = q.x * kv.x * INV; m[g][1] = q.y * kv.y * INV;
            m[g][2] = q.z * kv.z * INV; m[g][3] = q.w * kv.w * INV;
            s1 += m[g][0] + m[g][1] + m[g][2] + m[g][3];
            s2 += m[g][0] * m[g][0] + m[g][1] * m[g][1]
                + m[g][2] * m[g][2] + m[g][3] * m[g][3];
        }
        s1 += __shfl_xor_sync(0xffffffffu, s1, 1);
        s2 += __shfl_xor_sync(0xffffffffu, s2, 1);
        s1 += __shfl_xor_sync(0xffffffffu, s1, 2);
        s2 += __shfl_xor_sync(0xffffffffu, s2, 2);
        const float mean = s1 * (1.f / 192.f);
        const float rstd = rsqrtf(s2 * (1.f / 192.f) - mean * mean + 1e-5f);
        #pragma unroll
        for (int g = 0; g < 12; g++) {
            int j0 = g * 16 + ts * 4;
            float4 p1 = *(const float4*)(B1 + 128 + j0);
            float4 p2 = *(const float4*)(B2 + 320 + j0);
            float4 eu = *(const float4*)(EProw + 64 + j0);
            float4 gv = *(const float4*)(sG1 + j0);
            float4 bv = *(const float4*)(sB1 + j0);
            float x = (m[g][0] - mean) * rstd * gv.x + bv.x;
            m[g][0] = (p1.x + p2.x + eu.x) / (1.f + __expf(-x));
            x = (m[g][1] - mean) * rstd * gv.y + bv.y;
            m[g][1] = (p1.y + p2.y + eu.y) / (1.f + __expf(-x));
            x = (m[g][2] - mean) * rstd * gv.z + bv.z;
            m[g][2] = (p1.z + p2.z + eu.z) / (1.f + __expf(-x));
            x = (m[g][3] - mean) * rstd * gv.w + bv.w;
            m[g][3] = (p1.w + p2.w + eu.w) / (1.f + __expf(-x));
        }
    }
    __syncthreads();   // sEPU reads done; alias M and W over it

    // write mij fp16 to smem (stride 200) + load Wm tiles
    {
        const int e = tid >> 2, ts = tid & 3;
        #pragma unroll
        for (int g = 0; g < 12; g++) {
            int j0 = g * 16 + ts * 4;
            uint32_t off = (uint32_t)(e * 200 + j0) * 2;
            *(uint32_t*)(smc + F_M + off)     = h2(m[g][0], m[g][1]);
            *(uint32_t*)(smc + F_M + off + 4) = h2(m[g][2], m[g][3]);
        }
    }
    #pragma unroll
    for (int i = tid; i < 128 * 96; i += 256) {
        int n = i / 96, kk = (i % 96) * 2;
        uint32_t off = (uint32_t)(n * 200 + kk) * 2;
        *(uint32_t*)(smc + F_W + off) = *(const uint32_t*)(g_WmT + (size_t)n * 192 + kk);
    }
    __syncthreads();

    // ---- GEMM2: warp -> rows (w&3)*16, cols (w>>2)*64 ----
    {
        const int r0 = (w & 3) * 16, cb = (w >> 2) * 64;
        float d[8][4];
        #pragma unroll
        for (int nt = 0; nt < 8; nt++)
            d[nt][0] = d[nt][1] = d[nt][2] = d[nt][3] = 0.f;
        const uint32_t aoffb = (uint32_t)((r0 + (l & 15)) * 200 + (l >> 4) * 8) * 2;
        const int nrow = (l & 7) + ((l >> 4) << 3);
        const uint32_t boffb = (uint32_t)((cb + nrow) * 200 + ((l >> 3) & 1) * 8) * 2;
        #pragma unroll
        for (int kt = 0; kt < 12; kt++) {
            uint32_t aF[4];
            ldsm_x4(aF, smb + F_M + aoffb + kt * 32);
            #pragma unroll
            for (int nt = 0; nt < 4; nt++) {
                uint32_t bF[4];
                ldsm_x4(bF, smb + F_W + boffb + (uint32_t)(nt * 16 * 200) * 2 + kt * 32);
                mma_f16(d[2 * nt],     aF, bF);
                mma_f16(d[2 * nt + 1], aF, bF + 2);
            }
        }
        __syncthreads();   // W reads done; safe to write sMsg over W
        const int row = r0 + (l >> 2);
        #pragma unroll
        for (int nt = 0; nt < 8; nt++) {
            int col = cb + nt * 8 + 2 * (l & 3);
            sMsg[row * 132 + col]           = d[nt][0] + sBM[col];
            sMsg[row * 132 + col + 1]       = d[nt][1] + sBM[col + 1];
            sMsg[(row + 8) * 132 + col]     = d[nt][2] + sBM[col];
            sMsg[(row + 8) * 132 + col + 1] = d[nt][3] + sBM[col + 1];
        }
    }
    __syncthreads();

    // ---- LN2 + atomic scatter ----
    {
        const int r = tid >> 2, ts = tid & 3, c0 = ts * 32;
        const float* row = sMsg + r * 132;
        float4 vv[8];
        float s1 = 0.f, s2 = 0.f;
        #pragma unroll
        for (int q = 0; q < 8; q++) {
            vv[q] = *(const float4*)(row + c0 + q * 4);
            s1 += vv[q].x + vv[q].y + vv[q].z + vv[q].w;
            s2 += vv[q].x * vv[q].x + vv[q].y * vv[q].y + vv[q].z * vv[q].z + vv[q].w * vv[q].w;
        }
        s1 += __shfl_xor_sync(0xffffffffu, s1, 1);
        s2 += __shfl_xor_sync(0xffffffffu, s2, 1);
        s1 += __shfl_xor_sync(0xffffffffu, s1, 2);
        s2 += __shfl_xor_sync(0xffffffffu, s2, 2);
        const float mean = s1 * (1.f / 128.f);
        const float rstd = rsqrtf(s2 * (1.f / 128.f) - mean * mean + 1e-5f);
        if (e0 + r < E) {
            float* dst = out + (size_t)sI1[r] * 128 + c0;
            #pragma unroll
            for (int q = 0; q < 8; q++) {
                const float* v = (const float*)&vv[q];
                #pragma unroll
                for (int c = 0; c < 4; c++) {
                    int j = c0 + q * 4 + c;
                    atomicAdd(dst + q * 4 + c,
                              (v[c] - mean) * rstd * sG2[j] + sB2[j]);
                }
            }
        }
    }
}

extern "C" void kernel_launch(void* const* d_in, const int* in_sizes, int n_in,
                              void* d_out, int out_size) {
    const float* nf = (const float*)d_in[0];
    const void* i1 = d_in[1];
    const void* i2 = d_in[2];
    const float* ef = (const float*)d_in[3];
    const float *WQ = (const float*)d_in[4],  *bQ = (const float*)d_in[5];
    const float *WK = (const float*)d_in[6],  *bK = (const float*)d_in[7];
    const float *WV = (const float*)d_in[8],  *bV = (const float*)d_in[9];
    const float *WE = (const float*)d_in[10], *bE = (const float*)d_in[11];
    const float *Wu = (const float*)d_in[12], *bu = (const float*)d_in[13];
    const float *Wm = (const float*)d_in[14], *bm = (const float*)d_in[15];
    const float *g1 = (const float*)d_in[16], *b1 = (const float*)d_in[17];
    const float *g2 = (const float*)d_in[18], *b2 = (const float*)d_in[19];
    const int N = in_sizes[0] / 128;
    const int E = in_sizes[3] / 64;

    cudaFuncSetAttribute(edge_kernel, cudaFuncAttributeMaxDynamicSharedMemorySize, F_SMEM);

    zero_kernel<<<1024, 256>>>((float4*)d_out, out_size / 4);
    detect_kernel<<<1, 32>>>((const int*)i1, (const int*)i2, E);
    setup_kernel<<<160, 256>>>(WQ, bQ, WK, bK, WV, bV, WE, bE, Wu, bu);
    setup2_kernel<<<80, 256>>>(Wm);
    node_kernel<<<(N + 31) / 32, 256>>>(nf, N);
    edge_kernel<<<(E + 63) / 64, 256, F_SMEM>>>(
        ef, i1, i2, g1, b1, bm, g2, b2, (float*)d_out, E);
}

// round 9
// speedup vs baseline: 4.7770x; 1.0357x over previous
#include <cuda_runtime.h>
#include <cuda_bf16.h>
#include <cuda_fp16.h>
#include <cstdint>
#include <cstddef>

#define MAXN 50000
typedef unsigned long long ull;

__device__ __forceinline__ void ffma2(ull &acc, ull a, ull b) {
    asm("fma.rn.f32x2 %0, %1, %2, %0;" : "+l"(acc) : "l"(a), "l"(b));
}
__device__ __forceinline__ ull pack2(float lo, float hi) {
    ull r; asm("mov.b64 %0, {%1, %2};" : "=l"(r) : "f"(lo), "f"(hi)); return r;
}
__device__ __forceinline__ float2 unpack2(ull v) {
    float lo, hi; asm("mov.b64 {%0, %1}, %2;" : "=f"(lo), "=f"(hi) : "l"(v));
    return make_float2(lo, hi);
}
__device__ __forceinline__ uint32_t smem_u32(const void* p) {
    uint32_t a; asm("{ .reg .u64 t; cvta.to.shared.u64 t, %1; cvt.u32.u64 %0, t; }"
                    : "=r"(a) : "l"(p));
    return a;
}
__device__ __forceinline__ void ldsm_x4(uint32_t* a, uint32_t addr) {
    asm volatile("ldmatrix.sync.aligned.m8n8.x4.shared.b16 {%0,%1,%2,%3}, [%4];"
                 : "=r"(a[0]), "=r"(a[1]), "=r"(a[2]), "=r"(a[3]) : "r"(addr));
}
__device__ __forceinline__ void mma_f16(float* d, const uint32_t* a, const uint32_t* b) {
    asm volatile("mma.sync.aligned.m16n8k16.row.col.f32.f16.f16.f32 "
                 "{%0,%1,%2,%3},{%4,%5,%6,%7},{%8,%9},{%0,%1,%2,%3};"
                 : "+f"(d[0]), "+f"(d[1]), "+f"(d[2]), "+f"(d[3])
                 : "r"(a[0]), "r"(a[1]), "r"(a[2]), "r"(a[3]), "r"(b[0]), "r"(b[1]));
}
__device__ __forceinline__ uint32_t h2(float a, float b) {
    __half2 h = __floats2half2_rn(a, b);
    return *(uint32_t*)&h;
}

// ---------------- device globals ----------------
__device__ __align__(16) float g_Wnode[128 * 512];
__device__ __align__(16) float g_Wedge[64 * 256];
__device__ float g_bnode[512];
__device__ float g_bedge[256];
__device__ __align__(16) float g_G[(size_t)MAXN * 512];
__device__ __align__(8) __half g_WeT[256 * 64];    // [n][k] fp16
__device__ __align__(8) __half g_WmT[128 * 192];   // [n][k] fp16
__device__ int g_idx64;

__global__ void zero_kernel(float4* out, int n4) {
    for (int i = blockIdx.x * blockDim.x + threadIdx.x; i < n4; i += gridDim.x * blockDim.x)
        out[i] = make_float4(0.f, 0.f, 0.f, 0.f);
}
__global__ void detect_kernel(const int* a, const int* b, int E) {
    if (threadIdx.x == 0) {
        int n = E < 64 ? E : 64, ok = 1;
        for (int i = 0; i < n; i++)
            if (a[2 * i + 1] != 0 || b[2 * i + 1] != 0) ok = 0;
        g_idx64 = ok;
    }
}

__global__ void setup_kernel(const float* __restrict__ WQ, const float* __restrict__ bQ,
                             const float* __restrict__ WK, const float* __restrict__ bK,
                             const float* __restrict__ WV, const float* __restrict__ bV,
                             const float* __restrict__ WE, const float* __restrict__ bE,
                             const float* __restrict__ Wu, const float* __restrict__ bu) {
    const int total = 65536 + 16384 + 512 + 256;
    for (int t = blockIdx.x * blockDim.x + threadIdx.x; t < total; t += gridDim.x * blockDim.x) {
        float v;
        if (t < 65536) {
            int d = t >> 9, c = t & 511;
            if (c < 64)       v = WQ[d * 64 + c];
            else if (c < 128) v = WK[d * 64 + (c - 64)];
            else {
                int j = (c < 320) ? (c - 128) : (c - 320);
                int rb = (c < 320) ? 0 : 64;
                float s = 0.f;
                #pragma unroll 8
                for (int k = 0; k < 64; k++) s += WV[d * 64 + k] * Wu[(rb + k) * 192 + j];
                v = s;
            }
            g_Wnode[t] = v;
        } else if (t < 81920) {
            int t2 = t - 65536, r = t2 >> 8, c = t2 & 255;
            if (c < 64) v = WE[r * 64 + c];
            else {
                int j = c - 64; float s = 0.f;
                #pragma unroll 8
                for (int k = 0; k < 64; k++) s += WE[r * 64 + k] * Wu[(128 + k) * 192 + j];
                v = s;
            }
            g_Wedge[t2] = v;
        } else if (t < 82432) {
            int i = t - 81920;
            if (i < 64)       v = bQ[i];
            else if (i < 128) v = bK[i - 64];
            else {
                int j = (i < 320) ? (i - 128) : (i - 320);
                int rb = (i < 320) ? 0 : 64;
                float s = 0.f;
                #pragma unroll 8
                for (int k = 0; k < 64; k++) s += bV[k] * Wu[(rb + k) * 192 + j];
                v = s;
            }
            g_bnode[i] = v;
        } else {
            int i = t - 82432;
            if (i < 64) v = bE[i];
            else {
                int j = i - 64;
                float s = bu[j];
                #pragma unroll 8
                for (int k = 0; k < 64; k++) s += bE[k] * Wu[(128 + k) * 192 + j];
                v = s;
            }
            g_bedge[i] = v;
        }
    }
}

__global__ void setup2_kernel(const float* __restrict__ Wm) {
    const int total = 16384 + 24576;
    for (int t = blockIdx.x * blockDim.x + threadIdx.x; t < total; t += gridDim.x * blockDim.x) {
        if (t < 16384) {
            int n = t >> 6, k = t & 63;
            g_WeT[t] = __float2half_rn(g_Wedge[k * 256 + n]);
        } else {
            int t2 = t - 16384, n = t2 / 192, k = t2 % 192;
            g_WmT[t2] = __float2half_rn(Wm[k * 128 + n]);
        }
    }
}

// node kernel (known-good)
__global__ void __launch_bounds__(256) node_kernel(const float* __restrict__ nf, int N) {
    __shared__ float sA[32 * 260];
    const int tid = threadIdx.x, tile = blockIdx.x * 32;
    #pragma unroll
    for (int i = tid; i < 32 * 32; i += 256) {
        int r = i >> 5, c4 = (i & 31) << 2, n = tile + r;
        float4 v = make_float4(0.f, 0.f, 0.f, 0.f);
        if (n < N) v = *(const float4*)(nf + (size_t)n * 128 + c4);
        float2* dst = (float2*)(sA + r * 260 + 2 * c4);
        dst[0] = make_float2(v.x, v.x); dst[1] = make_float2(v.y, v.y);
        dst[2] = make_float2(v.z, v.z); dst[3] = make_float2(v.w, v.w);
    }
    __syncthreads();
    const int cg = tid & 63, rg = tid >> 6, c0 = cg * 8, r0 = rg * 8;
    ull acc[8][4];
    #pragma unroll
    for (int p = 0; p < 4; p++) {
        ull bb = pack2(g_bnode[c0 + 2 * p], g_bnode[c0 + 2 * p + 1]);
        #pragma unroll
        for (int r = 0; r < 8; r++) acc[r][p] = bb;
    }
    #pragma unroll 4
    for (int k = 0; k < 128; k++) {
        ulonglong2 w0 = *(const ulonglong2*)(g_Wnode + k * 512 + c0);
        ulonglong2 w1 = *(const ulonglong2*)(g_Wnode + k * 512 + c0 + 4);
        #pragma unroll
        for (int r = 0; r < 8; r++) {
            ull a2 = *(const ull*)(sA + (r0 + r) * 260 + 2 * k);
            ffma2(acc[r][0], a2, w0.x); ffma2(acc[r][1], a2, w0.y);
            ffma2(acc[r][2], a2, w1.x); ffma2(acc[r][3], a2, w1.y);
        }
    }
    #pragma unroll
    for (int r = 0; r < 8; r++) {
        int n = tile + r0 + r;
        if (n < N) {
            float2 p0 = unpack2(acc[r][0]), p1 = unpack2(acc[r][1]);
            float2 p2 = unpack2(acc[r][2]), p3 = unpack2(acc[r][3]);
            float4* dst = (float4*)(g_G + (size_t)n * 512 + c0);
            dst[0] = make_float4(p0.x, p0.y, p1.x, p1.y);
            dst[1] = make_float4(p2.x, p2.y, p3.x, p3.y);
        }
    }
}

// ================= fused edge kernel (TE=64, fp16, occ 2) =================
constexpr int F_A = 4096, F_B = 13312;
constexpr int F_EPU = 4096;
constexpr int F_M = 4096, F_W = 29696, F_MSG = 29696;
constexpr int F_SMEM = 81920;

__global__ void __launch_bounds__(256, 2) edge_kernel(
    const float* __restrict__ edge_fea,
    const void* __restrict__ idx1v, const void* __restrict__ idx2v,
    const float* __restrict__ g1, const float* __restrict__ b1,
    const float* __restrict__ bm,
    const float* __restrict__ g2, const float* __restrict__ b2,
    float* __restrict__ out, int E)
{
    extern __shared__ char smc[];
    const uint32_t smb = smem_u32(smc);
    int* sI1 = (int*)(smc);
    int* sI2 = (int*)(smc + 256);
    float* sBM = (float*)(smc + 512);
    float* sG2 = (float*)(smc + 1024);
    float* sB2 = (float*)(smc + 1536);
    float* sG1 = (float*)(smc + 2048);
    float* sB1 = (float*)(smc + 2816);
    float* sEPU = (float*)(smc + F_EPU);
    float* sMsg = (float*)(smc + F_MSG);
    const int tid = threadIdx.x, w = tid >> 5, l = tid & 31;
    const int e0 = blockIdx.x * 64;

    if (tid < 64) {
        int e = e0 + tid, i1 = 0, i2 = 0;
        if (e < E) {
            if (g_idx64) {
                i1 = (int)((const long long*)idx1v)[e];
                i2 = (int)((const long long*)idx2v)[e];
            } else {
                i1 = ((const int*)idx1v)[e];
                i2 = ((const int*)idx2v)[e];
            }
        }
        sI1[tid] = i1; sI2[tid] = i2;
    }
    if (tid < 128) { sBM[tid] = bm[tid]; sG2[tid] = g2[tid]; sB2[tid] = b2[tid]; }
    if (tid < 192) { sG1[tid] = g1[tid]; sB1[tid] = b1[tid]; }
    // A: edge_fea 64x64 -> fp16, stride 72
    #pragma unroll
    for (int i = tid; i < 64 * 16; i += 256) {
        int r = i >> 4, c4 = (i & 15) << 2, e = e0 + r;
        float4 v = make_float4(0.f, 0.f, 0.f, 0.f);
        if (e < E) v = *(const float4*)(edge_fea + (size_t)e * 64 + c4);
        uint32_t off = (uint32_t)(r * 72 + c4) * 2;
        *(uint32_t*)(smc + F_A + off)     = h2(v.x, v.y);
        *(uint32_t*)(smc + F_A + off + 4) = h2(v.z, v.w);
    }
    // B: WeT 256x64 fp16, stride 72
    #pragma unroll
    for (int i = tid; i < 256 * 32; i += 256) {
        int n = i >> 5, kk = (i & 31) * 2;
        uint32_t off = (uint32_t)(n * 72 + kk) * 2;
        *(uint32_t*)(smc + F_B + off) = *(const uint32_t*)(g_WeT + n * 64 + kk);
    }
    __syncthreads();

    // ---- GEMM1: warp -> rows (w&3)*16, cols (w>>2)*128 ----
    {
        const int r0 = (w & 3) * 16, cb = (w >> 2) * 128;
        float d[16][4];
        #pragma unroll
        for (int nt = 0; nt < 16; nt++)
            d[nt][0] = d[nt][1] = d[nt][2] = d[nt][3] = 0.f;
        const uint32_t aoffb = (uint32_t)((r0 + (l & 15)) * 72 + (l >> 4) * 8) * 2;
        const int nrow = (l & 7) + ((l >> 4) << 3);
        const uint32_t boffb = (uint32_t)((cb + nrow) * 72 + ((l >> 3) & 1) * 8) * 2;
        #pragma unroll
        for (int kt = 0; kt < 4; kt++) {
            uint32_t aF[4];
            ldsm_x4(aF, smb + F_A + aoffb + kt * 32);
            #pragma unroll
            for (int nt = 0; nt < 8; nt++) {
                uint32_t bF[4];
                ldsm_x4(bF, smb + F_B + boffb + (uint32_t)(nt * 16 * 72) * 2 + kt * 32);
                mma_f16(d[2 * nt],     aF, bF);
                mma_f16(d[2 * nt + 1], aF, bF + 2);
            }
        }
        __syncthreads();   // tile reads done; safe to write sEPU over A/B
        const int row = r0 + (l >> 2);
        #pragma unroll
        for (int nt = 0; nt < 16; nt++) {
            int col = cb + nt * 8 + 2 * (l & 3);
            sEPU[row * 260 + col]           = d[nt][0] + g_bedge[col];
            sEPU[row * 260 + col + 1]       = d[nt][1] + g_bedge[col + 1];
            sEPU[(row + 8) * 260 + col]     = d[nt][2] + g_bedge[col];
            sEPU[(row + 8) * 260 + col + 1] = d[nt][3] + g_bedge[col + 1];
        }
    }
    __syncthreads();

    // ---- attention: ONE gather pass (q,k,p1,p2 together); u stored over EU ----
    float m[12][4];
    {
        const int e = tid >> 2, ts = tid & 3;
        const float* B1 = g_G + (size_t)sI1[e] * 512;
        const float* B2 = g_G + (size_t)sI2[e] * 512;
        float* EProw = sEPU + e * 260;
        const float INV = 0.07216878364870323f;  // 1/sqrt(192)
        float s1 = 0.f, s2 = 0.f;
        #pragma unroll
        for (int g = 0; g < 12; g++) {
            int j0 = g * 16 + ts * 4;
            float4 q = *(const float4*)(B1 + (j0 & 63));
            float4 kv;
            if (j0 < 64)       kv = *(const float4*)(B1 + 64 + j0);
            else if (j0 < 128) kv = *(const float4*)(B2 + j0);
            else               kv = *(const float4*)(EProw + (j0 - 128));
            float4 p1 = *(const float4*)(B1 + 128 + j0);
            float4 p2 = *(const float4*)(B2 + 320 + j0);
            float4 eu = *(const float4*)(EProw + 64 + j0);
            m[g][0] = q.x * kv.x * INV; m[g][1] = q.y * kv.y * INV;
            m[g][2] = q.z * kv.z * INV; m[g][3] = q.w * kv.w * INV;
            s1 += m[g][0] + m[g][1] + m[g][2] + m[g][3];
            s2 += m[g][0] * m[g][0] + m[g][1] * m[g][1]
                + m[g][2] * m[g][2] + m[g][3] * m[g][3];
            eu.x += p1.x + p2.x; eu.y += p1.y + p2.y;
            eu.z += p1.z + p2.z; eu.w += p1.w + p2.w;
            *(float4*)(EProw + 64 + j0) = eu;   // u = P1 + P2 + EU (own addresses)
        }
        s1 += __shfl_xor_sync(0xffffffffu, s1, 1);
        s2 += __shfl_xor_sync(0xffffffffu, s2, 1);
        s1 += __shfl_xor_sync(0xffffffffu, s1, 2);
        s2 += __shfl_xor_sync(0xffffffffu, s2, 2);
        const float mean = s1 * (1.f / 192.f);
        const float rstd = rsqrtf(s2 * (1.f / 192.f) - mean * mean + 1e-5f);
        #pragma unroll
        for (int g = 0; g < 12; g++) {
            int j0 = g * 16 + ts * 4;
            float4 u  = *(const float4*)(EProw + 64 + j0);
            float4 gv = *(const float4*)(sG1 + j0);
            float4 bv = *(const float4*)(sB1 + j0);
            float x = (m[g][0] - mean) * rstd * gv.x + bv.x;
            m[g][0] = u.x / (1.f + __expf(-x));
            x = (m[g][1] - mean) * rstd * gv.y + bv.y;
            m[g][1] = u.y / (1.f + __expf(-x));
            x = (m[g][2] - mean) * rstd * gv.z + bv.z;
            m[g][2] = u.z / (1.f + __expf(-x));
            x = (m[g][3] - mean) * rstd * gv.w + bv.w;
            m[g][3] = u.w / (1.f + __expf(-x));
        }
    }
    __syncthreads();   // sEPU reads done; alias M and W over it

    // load Wm tiles first (long-latency global), then write mij fp16
    #pragma unroll
    for (int i = tid; i < 128 * 96; i += 256) {
        int n = i / 96, kk = (i % 96) * 2;
        uint32_t off = (uint32_t)(n * 200 + kk) * 2;
        *(uint32_t*)(smc + F_W + off) = *(const uint32_t*)(g_WmT + (size_t)n * 192 + kk);
    }
    {
        const int e = tid >> 2, ts = tid & 3;
        #pragma unroll
        for (int g = 0; g < 12; g++) {
            int j0 = g * 16 + ts * 4;
            uint32_t off = (uint32_t)(e * 200 + j0) * 2;
            *(uint32_t*)(smc + F_M + off)     = h2(m[g][0], m[g][1]);
            *(uint32_t*)(smc + F_M + off + 4) = h2(m[g][2], m[g][3]);
        }
    }
    __syncthreads();

    // ---- GEMM2: warp -> rows (w&3)*16, cols (w>>2)*64 ----
    {
        const int r0 = (w & 3) * 16, cb = (w >> 2) * 64;
        float d[8][4];
        #pragma unroll
        for (int nt = 0; nt < 8; nt++)
            d[nt][0] = d[nt][1] = d[nt][2] = d[nt][3] = 0.f;
        const uint32_t aoffb = (uint32_t)((r0 + (l & 15)) * 200 + (l >> 4) * 8) * 2;
        const int nrow = (l & 7) + ((l >> 4) << 3);
        const uint32_t boffb = (uint32_t)((cb + nrow) * 200 + ((l >> 3) & 1) * 8) * 2;
        #pragma unroll
        for (int kt = 0; kt < 12; kt++) {
            uint32_t aF[4];
            ldsm_x4(aF, smb + F_M + aoffb + kt * 32);
            #pragma unroll
            for (int nt = 0; nt < 4; nt++) {
                uint32_t bF[4];
                ldsm_x4(bF, smb + F_W + boffb + (uint32_t)(nt * 16 * 200) * 2 + kt * 32);
                mma_f16(d[2 * nt],     aF, bF);
                mma_f16(d[2 * nt + 1], aF, bF + 2);
            }
        }
        __syncthreads();   // W reads done; safe to write sMsg over W
        const int row = r0 + (l >> 2);
        #pragma unroll
        for (int nt = 0; nt < 8; nt++) {
            int col = cb + nt * 8 + 2 * (l & 3);
            sMsg[row * 132 + col]           = d[nt][0] + sBM[col];
            sMsg[row * 132 + col + 1]       = d[nt][1] + sBM[col + 1];
            sMsg[(row + 8) * 132 + col]     = d[nt][2] + sBM[col];
            sMsg[(row + 8) * 132 + col + 1] = d[nt][3] + sBM[col + 1];
        }
    }
    __syncthreads();

    // ---- LN2 + atomic scatter ----
    {
        const int r = tid >> 2, ts = tid & 3, c0 = ts * 32;
        const float* row = sMsg + r * 132;
        float4 vv[8];
        float s1 = 0.f, s2 = 0.f;
        #pragma unroll
        for (int q = 0; q < 8; q++) {
            vv[q] = *(const float4*)(row + c0 + q * 4);
            s1 += vv[q].x + vv[q].y + vv[q].z + vv[q].w;
            s2 += vv[q].x * vv[q].x + vv[q].y * vv[q].y + vv[q].z * vv[q].z + vv[q].w * vv[q].w;
        }
        s1 += __shfl_xor_sync(0xffffffffu, s1, 1);
        s2 += __shfl_xor_sync(0xffffffffu, s2, 1);
        s1 += __shfl_xor_sync(0xffffffffu, s1, 2);
        s2 += __shfl_xor_sync(0xffffffffu, s2, 2);
        const float mean = s1 * (1.f / 128.f);
        const float rstd = rsqrtf(s2 * (1.f / 128.f) - mean * mean + 1e-5f);
        if (e0 + r < E) {
            float* dst = out + (size_t)sI1[r] * 128 + c0;
            #pragma unroll
            for (int q = 0; q < 8; q++) {
                const float* v = (const float*)&vv[q];
                #pragma unroll
                for (int c = 0; c < 4; c++) {
                    int j = c0 + q * 4 + c;
                    atomicAdd(dst + q * 4 + c,
                              (v[c] - mean) * rstd * sG2[j] + sB2[j]);
                }
            }
        }
    }
}

extern "C" void kernel_launch(void* const* d_in, const int* in_sizes, int n_in,
                              void* d_out, int out_size) {
    const float* nf = (const float*)d_in[0];
    const void* i1 = d_in[1];
    const void* i2 = d_in[2];
    const float* ef = (const float*)d_in[3];
    const float *WQ = (const float*)d_in[4],  *bQ = (const float*)d_in[5];
    const float *WK = (const float*)d_in[6],  *bK = (const float*)d_in[7];
    const float *WV = (const float*)d_in[8],  *bV = (const float*)d_in[9];
    const float *WE = (const float*)d_in[10], *bE = (const float*)d_in[11];
    const float *Wu = (const float*)d_in[12], *bu = (const float*)d_in[13];
    const float *Wm = (const float*)d_in[14], *bm = (const float*)d_in[15];
    const float *g1 = (const float*)d_in[16], *b1 = (const float*)d_in[17];
    const float *g2 = (const float*)d_in[18], *b2 = (const float*)d_in[19];
    const int N = in_sizes[0] / 128;
    const int E = in_sizes[3] / 64;

    cudaFuncSetAttribute(edge_kernel, cudaFuncAttributeMaxDynamicSharedMemorySize, F_SMEM);

    zero_kernel<<<1024, 256>>>((float4*)d_out, out_size / 4);
    detect_kernel<<<1, 32>>>((const int*)i1, (const int*)i2, E);
    setup_kernel<<<160, 256>>>(WQ, bQ, WK, bK, WV, bV, WE, bE, Wu, bu);
    setup2_kernel<<<80, 256>>>(Wm);
    node_kernel<<<(N + 31) / 32, 256>>>(nf, N);
    edge_kernel<<<(E + 63) / 64, 256, F_SMEM>>>(
        ef, i1, i2, g1, b1, bm, g2, b2, (float*)d_out, E);
}